// round 1
// baseline (speedup 1.0000x reference)
#include <cuda_runtime.h>
#include <math.h>

#define NB 16
#define N4 (128*128)
#define N2 (256*256)
#define N1 (512*512)
#define KTOP 819

// ---------------- scratch (device globals; no runtime allocation) ----------------
__device__ float g_mask[NB * N4];                 // 1 MB   pixel mask at 128^2
__device__ float g_xh1[NB * N4 * 32];             // 32 MB  gelu(pw1(...)) NHWC
__device__ float g_gxsq[NB * 32];                 // GRN sum of squares
__device__ float g_nx[NB * 32];                   // GRN nx
__device__ float g_xres[NB * 32 * N4];            // 32 MB  residual output NCHW
__device__ float g_y[NB * 8 * N4];                // 8 MB   bn1(conv_up(x)) @128^2
__device__ float g_cat[NB * 16 * N2];             // 64 MB  concat(up2x(y), s) @256^2
__device__ float g_z[NB * 4 * N2];                // 16 MB  conv_last @256^2
__device__ float g_uz[NB * 4 * N1];               // 64 MB  up2x(z) @512^2

// ---------------- helpers ----------------
__device__ __forceinline__ float sigmoidf_(float x) { return 1.0f / (1.0f + expf(-x)); }

// ---------------- elementwise sigmoid (output part 2) ----------------
__global__ void sigmoid_kernel(const float* __restrict__ in, float* __restrict__ out, int n) {
    int i = blockIdx.x * 256 + threadIdx.x;
    if (i < n) out[i] = sigmoidf_(in[i]);
}

// ---------------- top-k threshold + mask (one block per batch) ----------------
__global__ __launch_bounds__(256) void topk_mask_kernel(const float* __restrict__ logits) {
    int b = blockIdx.x;
    int tid = threadIdx.x;
    unsigned key[64];
    const float* lp = logits + (size_t)b * N2;
#pragma unroll
    for (int i = 0; i < 64; i++) {
        int idx = tid + i * 256;
        int r = idx >> 7, c = idx & 127;
        float v = lp[(r * 2) * 256 + c * 2];           // [:, :, ::2, ::2]
        unsigned u = __float_as_uint(v);
        key[i] = (u & 0x80000000u) ? ~u : (u | 0x80000000u);  // order-preserving map
    }
    __shared__ int red[8];
    unsigned lo = 0u, hi = 0xFFFFFFFFu;
    while (lo < hi) {
        unsigned d = hi - lo;
        unsigned mid = lo + (d >> 1) + (d & 1u);       // ceil midpoint
        int cnt = 0;
#pragma unroll
        for (int i = 0; i < 64; i++) cnt += (key[i] >= mid) ? 1 : 0;
        for (int off = 16; off; off >>= 1) cnt += __shfl_xor_sync(0xffffffffu, cnt, off);
        if ((tid & 31) == 0) red[tid >> 5] = cnt;
        __syncthreads();
        int total = red[0] + red[1] + red[2] + red[3] + red[4] + red[5] + red[6] + red[7];
        if (total >= KTOP) lo = mid; else hi = mid - 1;
        __syncthreads();
    }
    // lo == k-th largest key value; mask = (key > thr)  (strict, matching flat > thr)
#pragma unroll
    for (int i = 0; i < 64; i++)
        g_mask[b * N4 + tid + i * 256] = (key[i] > lo) ? 1.0f : 0.0f;
}

__global__ void zero_gxsq_kernel() {
    if (threadIdx.x < NB * 32) g_gxsq[threadIdx.x] = 0.0f;
}

// ---------------- ConvNeXt block part 1: dw7x7 + mask + LN + mask + pw1 + gelu + sumsq ----------------
__global__ __launch_bounds__(256) void block1_kernel(
    const float* __restrict__ feats4x, const float* __restrict__ dw_w, const float* __restrict__ dw_b,
    const float* __restrict__ ln_g, const float* __restrict__ ln_b,
    const float* __restrict__ pw1_w, const float* __restrict__ pw1_b) {
    __shared__ float s_dw[32 * 49];
    __shared__ float s_pw1[32 * 32];
    __shared__ float s_tile[22 * 22];
    __shared__ float s_bsum[32];
    int tid = threadIdx.x;
    int tx = tid & 15, ty = tid >> 4;
    int b = blockIdx.z;
    int h0 = blockIdx.y * 16, w0 = blockIdx.x * 16;
    for (int i = tid; i < 32 * 49; i += 256) s_dw[i] = dw_w[i];
    for (int i = tid; i < 1024; i += 256) s_pw1[i] = pw1_w[i];
    if (tid < 32) s_bsum[tid] = 0.0f;
    __syncthreads();

    float acc[32];
    const float* fb = feats4x + (size_t)b * 32 * N4;
    for (int ci = 0; ci < 32; ci++) {
        const float* ip = fb + ci * N4;
        for (int i = tid; i < 484; i += 256) {
            int r = i / 22, c = i - r * 22;
            int gh = h0 + r - 3, gw = w0 + c - 3;
            float v = 0.0f;
            if (gh >= 0 && gh < 128 && gw >= 0 && gw < 128) v = ip[gh * 128 + gw];
            s_tile[i] = v;
        }
        __syncthreads();
        float s = 0.0f;
#pragma unroll
        for (int kh = 0; kh < 7; kh++)
#pragma unroll
            for (int kw = 0; kw < 7; kw++)
                s = fmaf(s_tile[(ty + kh) * 22 + tx + kw], s_dw[ci * 49 + kh * 7 + kw], s);
        acc[ci] = s + dw_b[ci];
        __syncthreads();
    }
    int h = h0 + ty, w = w0 + tx;
    float m = g_mask[b * N4 + h * 128 + w];
    float mu = 0.0f;
#pragma unroll
    for (int c = 0; c < 32; c++) { acc[c] *= m; mu += acc[c]; }
    mu *= (1.0f / 32.0f);
    float var = 0.0f;
#pragma unroll
    for (int c = 0; c < 32; c++) { float d = acc[c] - mu; var = fmaf(d, d, var); }
    var *= (1.0f / 32.0f);
    float rs = rsqrtf(var + 1e-6f);
#pragma unroll
    for (int c = 0; c < 32; c++)
        acc[c] = ((acc[c] - mu) * rs * ln_g[c] + ln_b[c]) * m;

    float y[32];
#pragma unroll
    for (int j = 0; j < 32; j++) {
        float t = pw1_b[j];
#pragma unroll
        for (int c = 0; c < 32; c++) t = fmaf(acc[c], s_pw1[j * 32 + c], t);
        y[j] = 0.5f * t * (1.0f + erff(t * 0.70710678118654752f));  // exact gelu
    }
    size_t base = ((size_t)(b * N4 + h * 128 + w)) * 32;
    float4* dst = reinterpret_cast<float4*>(g_xh1 + base);
#pragma unroll
    for (int q = 0; q < 8; q++)
        dst[q] = make_float4(y[4 * q], y[4 * q + 1], y[4 * q + 2], y[4 * q + 3]);

#pragma unroll
    for (int c = 0; c < 32; c++) {
        float v = y[c] * y[c];
        for (int off = 16; off; off >>= 1) v += __shfl_xor_sync(0xffffffffu, v, off);
        if ((tid & 31) == 0) atomicAdd(&s_bsum[c], v);
    }
    __syncthreads();
    if (tid < 32) atomicAdd(&g_gxsq[b * 32 + tid], s_bsum[tid]);
}

// ---------------- GRN stats: nx = gx / (mean_c gx + 1e-6) ----------------
__global__ void grn_kernel() {
    int b = threadIdx.x >> 5;
    int lane = threadIdx.x & 31;
    if (b < NB) {
        float g = sqrtf(g_gxsq[b * 32 + lane]);
        float s = g;
        for (int off = 16; off; off >>= 1) s += __shfl_xor_sync(0xffffffffu, s, off);
        float mean = s * (1.0f / 32.0f);
        g_nx[b * 32 + lane] = g / (mean + 1e-6f);
    }
}

// ---------------- ConvNeXt block part 2: GRN + pw2 + residual ----------------
__global__ __launch_bounds__(256) void block2_kernel(
    const float* __restrict__ feats4x,
    const float* __restrict__ grn_g, const float* __restrict__ grn_b,
    const float* __restrict__ pw2_w, const float* __restrict__ pw2_b) {
    __shared__ float s_pw2[1024];
    int tid = threadIdx.x;
    for (int i = tid; i < 1024; i += 256) s_pw2[i] = pw2_w[i];
    __syncthreads();
    int p = blockIdx.x * 256 + tid;
    int b = p >> 14, sp = p & 16383;
    float xh[32];
    const float4* src = reinterpret_cast<const float4*>(g_xh1 + (size_t)p * 32);
#pragma unroll
    for (int q = 0; q < 8; q++) {
        float4 v = src[q];
        xh[4 * q] = v.x; xh[4 * q + 1] = v.y; xh[4 * q + 2] = v.z; xh[4 * q + 3] = v.w;
    }
    float t[32];
#pragma unroll
    for (int c = 0; c < 32; c++) {
        float nx = g_nx[b * 32 + c];
        t[c] = fmaf(grn_g[c], xh[c] * nx, grn_b[c]) + xh[c];
    }
#pragma unroll
    for (int j = 0; j < 32; j++) {
        float o = pw2_b[j];
#pragma unroll
        for (int c = 0; c < 32; c++) o = fmaf(t[c], s_pw2[j * 32 + c], o);
        size_t idx = ((size_t)(b * 32 + j)) * N4 + sp;
        g_xres[idx] = feats4x[idx] + o;
    }
}

// ---------------- tiled 3x3 conv (+ optional BN / BN+ReLU) ----------------
template <int CIN, int COUT>
__global__ __launch_bounds__(256) void conv3x3_kernel(
    const float* __restrict__ in, int inChTot,
    const float* __restrict__ wgt, const float* __restrict__ bias,
    const float* __restrict__ bn_g, const float* __restrict__ bn_b,
    const float* __restrict__ bn_m, const float* __restrict__ bn_v,
    int mode,  // 0 none, 1 bn, 2 bn+relu
    float* __restrict__ out, int outChTot, int outChOff, int H, int W) {
    __shared__ float s_w[COUT * CIN * 9];
    __shared__ float s_tile[18 * 18];
    int tid = threadIdx.x;
    int tx = tid & 15, ty = tid >> 4;
    int b = blockIdx.z;
    int h0 = blockIdx.y * 16, w0 = blockIdx.x * 16;
    for (int i = tid; i < COUT * CIN * 9; i += 256) s_w[i] = wgt[i];
    float acc[COUT];
#pragma unroll
    for (int o = 0; o < COUT; o++) acc[o] = 0.0f;
    __syncthreads();
    for (int ci = 0; ci < CIN; ci++) {
        const float* ip = in + ((size_t)(b * inChTot + ci)) * H * W;
        for (int i = tid; i < 324; i += 256) {
            int r = i / 18, c = i - r * 18;
            int gh = h0 + r - 1, gw = w0 + c - 1;
            s_tile[i] = (gh >= 0 && gh < H && gw >= 0 && gw < W) ? ip[gh * W + gw] : 0.0f;
        }
        __syncthreads();
        float v[9];
#pragma unroll
        for (int kh = 0; kh < 3; kh++)
#pragma unroll
            for (int kw = 0; kw < 3; kw++)
                v[kh * 3 + kw] = s_tile[(ty + kh) * 18 + tx + kw];
#pragma unroll
        for (int o = 0; o < COUT; o++)
#pragma unroll
            for (int k = 0; k < 9; k++)
                acc[o] = fmaf(v[k], s_w[(o * CIN + ci) * 9 + k], acc[o]);
        __syncthreads();
    }
    int h = h0 + ty, w = w0 + tx;
#pragma unroll
    for (int o = 0; o < COUT; o++) {
        float r = acc[o] + bias[o];
        if (mode >= 1) {
            float sc = bn_g[o] * rsqrtf(bn_v[o] + 1e-5f);
            r = (r - bn_m[o]) * sc + bn_b[o];
        }
        if (mode == 2) r = fmaxf(r, 0.0f);
        out[((size_t)(b * outChTot + outChOff + o)) * H * W + h * W + w] = r;
    }
}

// ---------------- bilinear 2x upsample (jax.image.resize semantics) ----------------
__global__ void upsample2x_kernel(const float* __restrict__ in, float* __restrict__ out,
                                  int Cn, int Hs, int Ws, int inChTot, int outChTot, int outChOff) {
    int gid = blockIdx.x * 256 + threadIdx.x;
    int Wo = Ws * 2, Ho = Hs * 2;
    int total = NB * Cn * Ho * Wo;
    if (gid >= total) return;
    int ox = gid % Wo; int t = gid / Wo;
    int oy = t % Ho; t /= Ho;
    int c = t % Cn; int b = t / Cn;
    float fy = oy * 0.5f - 0.25f, fx = ox * 0.5f - 0.25f;
    int y0 = (int)floorf(fy), x0 = (int)floorf(fx);
    float wy = fy - (float)y0, wx = fx - (float)x0;
    int y0c = y0 < 0 ? 0 : y0;
    int y1c = (y0 + 1) > (Hs - 1) ? (Hs - 1) : (y0 + 1);
    int x0c = x0 < 0 ? 0 : x0;
    int x1c = (x0 + 1) > (Ws - 1) ? (Ws - 1) : (x0 + 1);
    const float* ip = in + ((size_t)(b * inChTot + c)) * Hs * Ws;
    float v00 = ip[y0c * Ws + x0c], v01 = ip[y0c * Ws + x1c];
    float v10 = ip[y1c * Ws + x0c], v11 = ip[y1c * Ws + x1c];
    float v = (1.0f - wy) * ((1.0f - wx) * v00 + wx * v01) + wy * ((1.0f - wx) * v10 + wx * v11);
    out[((size_t)(b * outChTot + outChOff + c)) * Ho * Wo + oy * Wo + ox] = v;
}

// ---------------- final 5x5 conv + sigmoid (output part 1) ----------------
__global__ __launch_bounds__(256) void conv5x5_sig_kernel(
    const float* __restrict__ w25, const float* __restrict__ bias, float* __restrict__ out) {
    __shared__ float s_w[4 * 25];
    __shared__ float s_tile[20 * 20];
    int tid = threadIdx.x;
    int tx = tid & 15, ty = tid >> 4;
    int b = blockIdx.z, h0 = blockIdx.y * 16, w0 = blockIdx.x * 16;
    if (tid < 100) s_w[tid] = w25[tid];
    float acc = bias[0];
    __syncthreads();
    for (int c = 0; c < 4; c++) {
        const float* ip = g_uz + ((size_t)(b * 4 + c)) * N1;
        for (int i = tid; i < 400; i += 256) {
            int r = i / 20, cc = i - r * 20;
            int gh = h0 + r - 2, gw = w0 + cc - 2;
            s_tile[i] = (gh >= 0 && gh < 512 && gw >= 0 && gw < 512) ? ip[gh * 512 + gw] : 0.0f;
        }
        __syncthreads();
#pragma unroll
        for (int kh = 0; kh < 5; kh++)
#pragma unroll
            for (int kw = 0; kw < 5; kw++)
                acc = fmaf(s_tile[(ty + kh) * 20 + tx + kw], s_w[c * 25 + kh * 5 + kw], acc);
        __syncthreads();
    }
    int h = h0 + ty, w = w0 + tx;
    out[(size_t)b * N1 + h * 512 + w] = sigmoidf_(acc);
}

// ---------------- launcher ----------------
extern "C" void kernel_launch(void* const* d_in, const int* in_sizes, int n_in,
                              void* d_out, int out_size) {
    const float* feats4x = (const float*)d_in[0];
    const float* feats2x = (const float*)d_in[1];
    const float* logits  = (const float*)d_in[2];
    const float* dw_w  = (const float*)d_in[3];
    const float* dw_b  = (const float*)d_in[4];
    const float* ln_g  = (const float*)d_in[5];
    const float* ln_b  = (const float*)d_in[6];
    const float* pw1_w = (const float*)d_in[7];
    const float* pw1_b = (const float*)d_in[8];
    const float* grn_g = (const float*)d_in[9];
    const float* grn_b = (const float*)d_in[10];
    const float* pw2_w = (const float*)d_in[11];
    const float* pw2_b = (const float*)d_in[12];
    const float* up_w  = (const float*)d_in[13];
    const float* up_b  = (const float*)d_in[14];
    const float* bn1_g = (const float*)d_in[15];
    const float* bn1_b = (const float*)d_in[16];
    const float* bn1_m = (const float*)d_in[17];
    const float* bn1_v = (const float*)d_in[18];
    const float* sh_w  = (const float*)d_in[19];
    const float* sh_b  = (const float*)d_in[20];
    const float* bn2_g = (const float*)d_in[21];
    const float* bn2_b = (const float*)d_in[22];
    const float* bn2_m = (const float*)d_in[23];
    const float* bn2_v = (const float*)d_in[24];
    const float* last_w  = (const float*)d_in[25];
    const float* last_b  = (const float*)d_in[26];
    const float* last2_w = (const float*)d_in[27];
    const float* last2_b = (const float*)d_in[28];
    float* out = (float*)d_out;

    float *p_xres, *p_y, *p_cat, *p_z, *p_uz;
    cudaGetSymbolAddress((void**)&p_xres, g_xres);
    cudaGetSymbolAddress((void**)&p_y, g_y);
    cudaGetSymbolAddress((void**)&p_cat, g_cat);
    cudaGetSymbolAddress((void**)&p_z, g_z);
    cudaGetSymbolAddress((void**)&p_uz, g_uz);

    // output part 2: sigmoid(classify_logits), 16*256*256 elems after first 16*512*512
    sigmoid_kernel<<<(NB * N2 + 255) / 256, 256>>>(logits, out + (size_t)NB * N1, NB * N2);
    // top-k mask
    topk_mask_kernel<<<NB, 256>>>(logits);
    zero_gxsq_kernel<<<1, 512>>>();
    // ConvNeXt block
    block1_kernel<<<dim3(8, 8, NB), 256>>>(feats4x, dw_w, dw_b, ln_g, ln_b, pw1_w, pw1_b);
    grn_kernel<<<1, 512>>>();
    block2_kernel<<<(NB * N4) / 256, 256>>>(feats4x, grn_g, grn_b, pw2_w, pw2_b);
    // up branch: conv 32->8 + bn1 @128^2, then upsample into cat channels 0..7
    conv3x3_kernel<32, 8><<<dim3(8, 8, NB), 256>>>(p_xres, 32, up_w, up_b,
        bn1_g, bn1_b, bn1_m, bn1_v, 1, p_y, 8, 0, 128, 128);
    upsample2x_kernel<<<(NB * 8 * N2 + 255) / 256, 256>>>(p_y, p_cat, 8, 128, 128, 8, 16, 0);
    // shortcut branch: conv 16->8 + bn2 + relu @256^2 into cat channels 8..15
    conv3x3_kernel<16, 8><<<dim3(16, 16, NB), 256>>>(feats2x, 16, sh_w, sh_b,
        bn2_g, bn2_b, bn2_m, bn2_v, 2, p_cat, 16, 8, 256, 256);
    // last conv 16->4 @256^2
    conv3x3_kernel<16, 4><<<dim3(16, 16, NB), 256>>>(p_cat, 16, last_w, last_b,
        nullptr, nullptr, nullptr, nullptr, 0, p_z, 4, 0, 256, 256);
    // upsample z to 512^2
    upsample2x_kernel<<<(NB * 4 * N1 + 255) / 256, 256>>>(p_z, p_uz, 4, 256, 256, 4, 4, 0);
    // final 5x5 conv + sigmoid -> output part 1
    conv5x5_sig_kernel<<<dim3(32, 32, NB), 256>>>(last2_w, last2_b, out);
}

// round 3
// speedup vs baseline: 1.5212x; 1.5212x over previous
#include <cuda_runtime.h>
#include <math.h>

#define NB 16
#define N4 (128*128)
#define N2 (256*256)
#define N1 (512*512)
#define KTOP 819

// ---------------- scratch (device globals) ----------------
__device__ float g_mask[NB * N4];                 // mask at 128^2
__device__ float g_dwout[NB * 32 * N4];           // dw-conv output NCHW
__device__ float g_xh1[NB * N4 * 32];             // gelu(pw1(...)) NHWC
__device__ float g_gxsq[NB * 32];
__device__ float g_nx[NB * 32];
__device__ float g_xres[NB * 32 * N4];            // residual output NCHW
__device__ float g_y[NB * 8 * N4];                // bn1(conv_up(x)) @128^2
__device__ float g_cat[NB * 16 * N2];             // concat buffer @256^2
__device__ float g_z[NB * 4 * N2];                // conv_last @256^2

__device__ __forceinline__ float sigmoidf_(float x) { return 1.0f / (1.0f + expf(-x)); }

// ---------------- sigmoid (output part 2), vectorized ----------------
__global__ void sigmoid4_kernel(const float4* __restrict__ in, float4* __restrict__ out, int n4) {
    int i = blockIdx.x * 256 + threadIdx.x;
    if (i < n4) {
        float4 v = in[i];
        out[i] = make_float4(sigmoidf_(v.x), sigmoidf_(v.y), sigmoidf_(v.z), sigmoidf_(v.w));
    }
}

// ---------------- top-k threshold + mask ----------------
__global__ __launch_bounds__(256) void topk_mask_kernel(const float* __restrict__ logits) {
    int b = blockIdx.x;
    int tid = threadIdx.x;
    unsigned key[64];
    const float* lp = logits + (size_t)b * N2;
#pragma unroll
    for (int i = 0; i < 64; i++) {
        int idx = tid + i * 256;
        int r = idx >> 7, c = idx & 127;
        float v = lp[(r * 2) * 256 + c * 2];
        unsigned u = __float_as_uint(v);
        key[i] = (u & 0x80000000u) ? ~u : (u | 0x80000000u);
    }
    __shared__ int red[8];
    unsigned lo = 0u, hi = 0xFFFFFFFFu;
    while (lo < hi) {
        unsigned d = hi - lo;
        unsigned mid = lo + (d >> 1) + (d & 1u);
        int cnt = 0;
#pragma unroll
        for (int i = 0; i < 64; i++) cnt += (key[i] >= mid) ? 1 : 0;
        for (int off = 16; off; off >>= 1) cnt += __shfl_xor_sync(0xffffffffu, cnt, off);
        if ((tid & 31) == 0) red[tid >> 5] = cnt;
        __syncthreads();
        int total = red[0] + red[1] + red[2] + red[3] + red[4] + red[5] + red[6] + red[7];
        if (total >= KTOP) lo = mid; else hi = mid - 1;
        __syncthreads();
    }
#pragma unroll
    for (int i = 0; i < 64; i++)
        g_mask[b * N4 + tid + i * 256] = (key[i] > lo) ? 1.0f : 0.0f;
}

__global__ void zero_gxsq_kernel() {
    if (threadIdx.x < NB * 32) g_gxsq[threadIdx.x] = 0.0f;
}

// ---------------- kernel A: depthwise 7x7 conv, 2x2 px/thread ----------------
// grid (4,4,NB), 256 threads (16x16), tile 32x32 output, halo 3 -> 38x38 input tile.
__global__ __launch_bounds__(256) void dwconv_kernel(
    const float* __restrict__ feats4x, const float* __restrict__ dw_w, const float* __restrict__ dw_b) {
    __shared__ float s_dw[32 * 49];
    __shared__ float s_tile[2][38 * 38];
    int tid = threadIdx.x;
    int tx = tid & 15, ty = tid >> 4;
    int b = blockIdx.z;
    int h0 = blockIdx.y * 32, w0 = blockIdx.x * 32;
    for (int i = tid; i < 32 * 49; i += 256) s_dw[i] = dw_w[i];
    const float* fb = feats4x + (size_t)b * 32 * N4;

    // preload tile for channel 0
    {
        const float* ip = fb;
        for (int i = tid; i < 38 * 38; i += 256) {
            int r = i / 38, c = i - r * 38;
            int gh = h0 + r - 3, gw = w0 + c - 3;
            s_tile[0][i] = (gh >= 0 && gh < 128 && gw >= 0 && gw < 128) ? ip[gh * 128 + gw] : 0.0f;
        }
    }
    __syncthreads();

    int bty = 2 * ty, btx = 2 * tx;
    for (int ci = 0; ci < 32; ci++) {
        int cur = ci & 1;
        if (ci + 1 < 32) {
            const float* ip = fb + (size_t)(ci + 1) * N4;
            float* dstT = s_tile[cur ^ 1];
            for (int i = tid; i < 38 * 38; i += 256) {
                int r = i / 38, c = i - r * 38;
                int gh = h0 + r - 3, gw = w0 + c - 3;
                dstT[i] = (gh >= 0 && gh < 128 && gw >= 0 && gw < 128) ? ip[gh * 128 + gw] : 0.0f;
            }
        }
        const float* st = s_tile[cur];
        const float* wp_base = s_dw + ci * 49;
        float a00 = 0.f, a01 = 0.f, a10 = 0.f, a11 = 0.f;
        float wp[7];
#pragma unroll
        for (int ir = 0; ir < 8; ir++) {
            float t[8];
#pragma unroll
            for (int c = 0; c < 8; c++) t[c] = st[(bty + ir) * 38 + btx + c];
            float wr[7];
            if (ir < 7) {
#pragma unroll
                for (int k = 0; k < 7; k++) wr[k] = wp_base[ir * 7 + k];
#pragma unroll
                for (int k = 0; k < 7; k++) {
                    a00 = fmaf(t[k], wr[k], a00);
                    a01 = fmaf(t[k + 1], wr[k], a01);
                }
            }
            if (ir >= 1) {
#pragma unroll
                for (int k = 0; k < 7; k++) {
                    a10 = fmaf(t[k], wp[k], a10);
                    a11 = fmaf(t[k + 1], wp[k], a11);
                }
            }
#pragma unroll
            for (int k = 0; k < 7; k++) wp[k] = wr[k];
        }
        float bias = dw_b[ci];
        float* op = g_dwout + ((size_t)(b * 32 + ci)) * N4 + (h0 + bty) * 128 + w0 + btx;
        *reinterpret_cast<float2*>(op) = make_float2(a00 + bias, a01 + bias);
        *reinterpret_cast<float2*>(op + 128) = make_float2(a10 + bias, a11 + bias);
        __syncthreads();
    }
}

// ---------------- kernel B: mask + LN + pw1 + gelu + sumsq ----------------
__global__ __launch_bounds__(256) void lnpw1_kernel(
    const float* __restrict__ ln_g, const float* __restrict__ ln_b,
    const float* __restrict__ pw1_w, const float* __restrict__ pw1_b) {
    __shared__ float s_pw1[1024];
    __shared__ float s_lng[32], s_lnb[32], s_pb[32];
    __shared__ float s_bsum[32];
    int tid = threadIdx.x;
    for (int i = tid; i < 1024; i += 256) s_pw1[i] = pw1_w[i];
    if (tid < 32) { s_lng[tid] = ln_g[tid]; s_lnb[tid] = ln_b[tid]; s_pb[tid] = pw1_b[tid]; s_bsum[tid] = 0.0f; }
    __syncthreads();

    int p = blockIdx.x * 256 + tid;
    int b = p >> 14, sp = p & 16383;
    float v[32];
#pragma unroll
    for (int c = 0; c < 32; c++) v[c] = g_dwout[((size_t)(b * 32 + c)) * N4 + sp];
    float m = g_mask[p];
    float mu = 0.0f;
#pragma unroll
    for (int c = 0; c < 32; c++) { v[c] *= m; mu += v[c]; }
    mu *= (1.0f / 32.0f);
    float var = 0.0f;
#pragma unroll
    for (int c = 0; c < 32; c++) { float d = v[c] - mu; var = fmaf(d, d, var); }
    var *= (1.0f / 32.0f);
    float rs = rsqrtf(var + 1e-6f);
#pragma unroll
    for (int c = 0; c < 32; c++)
        v[c] = ((v[c] - mu) * rs * s_lng[c] + s_lnb[c]) * m;

    float4* dst = reinterpret_cast<float4*>(g_xh1 + (size_t)p * 32);
    const float4* wf4 = reinterpret_cast<const float4*>(s_pw1);
#pragma unroll
    for (int jq = 0; jq < 8; jq++) {
        float y4[4];
#pragma unroll
        for (int u = 0; u < 4; u++) {
            int j = jq * 4 + u;
            float t = s_pb[j];
#pragma unroll
            for (int cq = 0; cq < 8; cq++) {
                float4 w = wf4[j * 8 + cq];
                t = fmaf(v[4 * cq], w.x, t);
                t = fmaf(v[4 * cq + 1], w.y, t);
                t = fmaf(v[4 * cq + 2], w.z, t);
                t = fmaf(v[4 * cq + 3], w.w, t);
            }
            float g = 0.5f * t * (1.0f + erff(t * 0.70710678118654752f));
            y4[u] = g;
            float sq = g * g;
            for (int off = 16; off; off >>= 1) sq += __shfl_xor_sync(0xffffffffu, sq, off);
            if ((tid & 31) == 0) atomicAdd(&s_bsum[j], sq);
        }
        dst[jq] = make_float4(y4[0], y4[1], y4[2], y4[3]);
    }
    __syncthreads();
    if (tid < 32) atomicAdd(&g_gxsq[b * 32 + tid], s_bsum[tid]);
}

// ---------------- GRN stats ----------------
__global__ void grn_kernel() {
    int b = threadIdx.x >> 5;
    int lane = threadIdx.x & 31;
    if (b < NB) {
        float g = sqrtf(g_gxsq[b * 32 + lane]);
        float s = g;
        for (int off = 16; off; off >>= 1) s += __shfl_xor_sync(0xffffffffu, s, off);
        float mean = s * (1.0f / 32.0f);
        g_nx[b * 32 + lane] = g / (mean + 1e-6f);
    }
}

// ---------------- block2: GRN + pw2 + residual ----------------
__global__ __launch_bounds__(256) void block2_kernel(
    const float* __restrict__ feats4x,
    const float* __restrict__ grn_g, const float* __restrict__ grn_b,
    const float* __restrict__ pw2_w, const float* __restrict__ pw2_b) {
    __shared__ float s_pw2[1024];
    __shared__ float s_gg[32], s_gb[32], s_pb[32];
    int tid = threadIdx.x;
    for (int i = tid; i < 1024; i += 256) s_pw2[i] = pw2_w[i];
    if (tid < 32) { s_gg[tid] = grn_g[tid]; s_gb[tid] = grn_b[tid]; s_pb[tid] = pw2_b[tid]; }
    __syncthreads();
    int p = blockIdx.x * 256 + tid;
    int b = p >> 14, sp = p & 16383;
    float t[32];
    const float4* src = reinterpret_cast<const float4*>(g_xh1 + (size_t)p * 32);
#pragma unroll
    for (int q = 0; q < 8; q++) {
        float4 v = src[q];
        t[4 * q] = v.x; t[4 * q + 1] = v.y; t[4 * q + 2] = v.z; t[4 * q + 3] = v.w;
    }
#pragma unroll
    for (int c = 0; c < 32; c++) {
        float nx = g_nx[b * 32 + c];
        t[c] = fmaf(s_gg[c], t[c] * nx, s_gb[c]) + t[c];
    }
    const float4* wf4 = reinterpret_cast<const float4*>(s_pw2);
#pragma unroll
    for (int j = 0; j < 32; j++) {
        float o = s_pb[j];
#pragma unroll
        for (int cq = 0; cq < 8; cq++) {
            float4 w = wf4[j * 8 + cq];
            o = fmaf(t[4 * cq], w.x, o);
            o = fmaf(t[4 * cq + 1], w.y, o);
            o = fmaf(t[4 * cq + 2], w.z, o);
            o = fmaf(t[4 * cq + 3], w.w, o);
        }
        size_t idx = ((size_t)(b * 32 + j)) * N4 + sp;
        g_xres[idx] = feats4x[idx] + o;
    }
}

// ---------------- register-blocked 3x3 conv: 2x2 px/thread, 32x32 tile ----------------
template <int CIN, int COUT>
__global__ __launch_bounds__(256) void conv3x3_rb_kernel(
    const float* __restrict__ in, int inChTot,
    const float* __restrict__ wgt, const float* __restrict__ bias,
    const float* __restrict__ bn_g, const float* __restrict__ bn_b,
    const float* __restrict__ bn_m, const float* __restrict__ bn_v,
    int mode,  // 0 none, 1 bn, 2 bn+relu
    float* __restrict__ out, int outChTot, int outChOff, int H, int W) {
    __shared__ float s_w[COUT * CIN * 12];
    __shared__ float s_tile[2][34 * 34];
    int tid = threadIdx.x;
    int tx = tid & 15, ty = tid >> 4;
    int b = blockIdx.z;
    int h0 = blockIdx.y * 32, w0 = blockIdx.x * 32;
    for (int i = tid; i < COUT * CIN * 12; i += 256) {
        int q = i / 12, k = i - q * 12;
        s_w[i] = (k < 9) ? wgt[q * 9 + k] : 0.0f;
    }
    {
        const float* ip = in + ((size_t)(b * inChTot)) * H * W;
        for (int i = tid; i < 34 * 34; i += 256) {
            int r = i / 34, c = i - r * 34;
            int gh = h0 + r - 1, gw = w0 + c - 1;
            s_tile[0][i] = (gh >= 0 && gh < H && gw >= 0 && gw < W) ? ip[gh * W + gw] : 0.0f;
        }
    }
    float acc[COUT][4];
#pragma unroll
    for (int o = 0; o < COUT; o++)
#pragma unroll
        for (int u = 0; u < 4; u++) acc[o][u] = 0.0f;
    __syncthreads();

    int bty = 2 * ty, btx = 2 * tx;
    for (int ci = 0; ci < CIN; ci++) {
        int cur = ci & 1;
        if (ci + 1 < CIN) {
            const float* ip = in + ((size_t)(b * inChTot + ci + 1)) * H * W;
            float* dstT = s_tile[cur ^ 1];
            for (int i = tid; i < 34 * 34; i += 256) {
                int r = i / 34, c = i - r * 34;
                int gh = h0 + r - 1, gw = w0 + c - 1;
                dstT[i] = (gh >= 0 && gh < H && gw >= 0 && gw < W) ? ip[gh * W + gw] : 0.0f;
            }
        }
        const float* st = s_tile[cur];
        float t[16];
#pragma unroll
        for (int r = 0; r < 4; r++)
#pragma unroll
            for (int c = 0; c < 4; c++)
                t[r * 4 + c] = st[(bty + r) * 34 + btx + c];
#pragma unroll
        for (int o = 0; o < COUT; o++) {
            const float* wb = s_w + (o * CIN + ci) * 12;
            float4 wa = *reinterpret_cast<const float4*>(wb);
            float4 wbv = *reinterpret_cast<const float4*>(wb + 4);
            float w8 = wb[8];
            // w[kh*3+kw]: wa = w0..w3, wbv = w4..w7, w8
#pragma unroll
            for (int r = 0; r < 2; r++)
#pragma unroll
                for (int c = 0; c < 2; c++) {
                    float a = acc[o][r * 2 + c];
                    a = fmaf(t[(r + 0) * 4 + c + 0], wa.x, a);
                    a = fmaf(t[(r + 0) * 4 + c + 1], wa.y, a);
                    a = fmaf(t[(r + 0) * 4 + c + 2], wa.z, a);
                    a = fmaf(t[(r + 1) * 4 + c + 0], wa.w, a);
                    a = fmaf(t[(r + 1) * 4 + c + 1], wbv.x, a);
                    a = fmaf(t[(r + 1) * 4 + c + 2], wbv.y, a);
                    a = fmaf(t[(r + 2) * 4 + c + 0], wbv.z, a);
                    a = fmaf(t[(r + 2) * 4 + c + 1], wbv.w, a);
                    a = fmaf(t[(r + 2) * 4 + c + 2], w8, a);
                    acc[o][r * 2 + c] = a;
                }
        }
        __syncthreads();
    }
#pragma unroll
    for (int o = 0; o < COUT; o++) {
        float bs = bias[o];
        float sc = 1.0f, sh = 0.0f;
        if (mode >= 1) {
            sc = bn_g[o] * rsqrtf(bn_v[o] + 1e-5f);
            sh = bn_b[o] - bn_m[o] * sc;
        }
        float* op = out + ((size_t)(b * outChTot + outChOff + o)) * H * W + (h0 + bty) * W + w0 + btx;
#pragma unroll
        for (int r = 0; r < 2; r++) {
            float r0 = acc[o][r * 2 + 0] + bs;
            float r1 = acc[o][r * 2 + 1] + bs;
            if (mode >= 1) { r0 = fmaf(r0, sc, sh); r1 = fmaf(r1, sc, sh); }
            if (mode == 2) { r0 = fmaxf(r0, 0.0f); r1 = fmaxf(r1, 0.0f); }
            *reinterpret_cast<float2*>(op + r * W) = make_float2(r0, r1);
        }
    }
}

// ---------------- bilinear 2x upsample (y -> cat channels 0..7) ----------------
__global__ void upsample2x_kernel(const float* __restrict__ in, float* __restrict__ out,
                                  int Cn, int Hs, int Ws, int inChTot, int outChTot, int outChOff) {
    int gid = blockIdx.x * 256 + threadIdx.x;
    int Wo = Ws * 2, Ho = Hs * 2;
    int total = NB * Cn * Ho * Wo;
    if (gid >= total) return;
    int ox = gid % Wo; int t = gid / Wo;
    int oy = t % Ho; t /= Ho;
    int c = t % Cn; int b = t / Cn;
    float fy = oy * 0.5f - 0.25f, fx = ox * 0.5f - 0.25f;
    int y0 = (int)floorf(fy), x0 = (int)floorf(fx);
    float wy = fy - (float)y0, wx = fx - (float)x0;
    int y0c = y0 < 0 ? 0 : y0;
    int y1c = (y0 + 1) > (Hs - 1) ? (Hs - 1) : (y0 + 1);
    int x0c = x0 < 0 ? 0 : x0;
    int x1c = (x0 + 1) > (Ws - 1) ? (Ws - 1) : (x0 + 1);
    const float* ip = in + ((size_t)(b * inChTot + c)) * Hs * Ws;
    float v00 = ip[y0c * Ws + x0c], v01 = ip[y0c * Ws + x1c];
    float v10 = ip[y1c * Ws + x0c], v11 = ip[y1c * Ws + x1c];
    float v = (1.0f - wy) * ((1.0f - wx) * v00 + wx * v01) + wy * ((1.0f - wx) * v10 + wx * v11);
    out[((size_t)(b * outChTot + outChOff + c)) * Ho * Wo + oy * Wo + ox] = v;
}

// ---------------- fused: up2x(z) -> conv5x5 -> sigmoid, 2x2 px/thread ----------------
// grid (16,16,NB): 32x32 output tile @512^2. uz tile 36x36 built in shared from z (256^2).
__global__ __launch_bounds__(256) void conv5x5up_sig_kernel(
    const float* __restrict__ w25, const float* __restrict__ bias, float* __restrict__ out) {
    __shared__ float s_w[4 * 28];
    __shared__ float s_uz[36 * 36];
    int tid = threadIdx.x;
    int tx = tid & 15, ty = tid >> 4;
    int b = blockIdx.z, h0 = blockIdx.y * 32, w0 = blockIdx.x * 32;
    if (tid < 112) {
        int ch = tid / 28, k = tid % 28;
        s_w[tid] = (k < 25) ? w25[ch * 25 + k] : 0.0f;
    }
    float acc[4] = {0.f, 0.f, 0.f, 0.f};
    int bty = 2 * ty, btx = 2 * tx;
    for (int ch = 0; ch < 4; ch++) {
        __syncthreads();
        const float* zp = g_z + ((size_t)(b * 4 + ch)) * N2;
        for (int i = tid; i < 36 * 36; i += 256) {
            int r = i / 36, c = i - r * 36;
            int oy = h0 - 2 + r, ox = w0 - 2 + c;
            float v = 0.0f;
            if (oy >= 0 && oy < 512 && ox >= 0 && ox < 512) {
                float fy = oy * 0.5f - 0.25f, fx = ox * 0.5f - 0.25f;
                int y0 = (int)floorf(fy), x0 = (int)floorf(fx);
                float wy = fy - (float)y0, wx = fx - (float)x0;
                int y0c = y0 < 0 ? 0 : y0;
                int y1c = (y0 + 1) > 255 ? 255 : (y0 + 1);
                int x0c = x0 < 0 ? 0 : x0;
                int x1c = (x0 + 1) > 255 ? 255 : (x0 + 1);
                float v00 = zp[y0c * 256 + x0c], v01 = zp[y0c * 256 + x1c];
                float v10 = zp[y1c * 256 + x0c], v11 = zp[y1c * 256 + x1c];
                v = (1.0f - wy) * ((1.0f - wx) * v00 + wx * v01)
                  + wy * ((1.0f - wx) * v10 + wx * v11);
            }
            s_uz[i] = v;
        }
        __syncthreads();
        float t[36];
#pragma unroll
        for (int r = 0; r < 6; r++)
#pragma unroll
            for (int c = 0; c < 6; c++)
                t[r * 6 + c] = s_uz[(bty + r) * 36 + btx + c];
        const float* wb = s_w + ch * 28;
#pragma unroll
        for (int r = 0; r < 2; r++)
#pragma unroll
            for (int c = 0; c < 2; c++) {
                float a = acc[r * 2 + c];
#pragma unroll
                for (int kh = 0; kh < 5; kh++)
#pragma unroll
                    for (int kw = 0; kw < 5; kw++)
                        a = fmaf(t[(r + kh) * 6 + c + kw], wb[kh * 5 + kw], a);
                acc[r * 2 + c] = a;
            }
    }
    float bs = bias[0];
    float* op = out + (size_t)b * N1 + (h0 + bty) * 512 + w0 + btx;
#pragma unroll
    for (int r = 0; r < 2; r++) {
        float r0 = sigmoidf_(acc[r * 2 + 0] + bs);
        float r1 = sigmoidf_(acc[r * 2 + 1] + bs);
        *reinterpret_cast<float2*>(op + r * 512) = make_float2(r0, r1);
    }
}

// ---------------- launcher ----------------
extern "C" void kernel_launch(void* const* d_in, const int* in_sizes, int n_in,
                              void* d_out, int out_size) {
    const float* feats4x = (const float*)d_in[0];
    const float* feats2x = (const float*)d_in[1];
    const float* logits  = (const float*)d_in[2];
    const float* dw_w  = (const float*)d_in[3];
    const float* dw_b  = (const float*)d_in[4];
    const float* ln_g  = (const float*)d_in[5];
    const float* ln_b  = (const float*)d_in[6];
    const float* pw1_w = (const float*)d_in[7];
    const float* pw1_b = (const float*)d_in[8];
    const float* grn_g = (const float*)d_in[9];
    const float* grn_b = (const float*)d_in[10];
    const float* pw2_w = (const float*)d_in[11];
    const float* pw2_b = (const float*)d_in[12];
    const float* up_w  = (const float*)d_in[13];
    const float* up_b  = (const float*)d_in[14];
    const float* bn1_g = (const float*)d_in[15];
    const float* bn1_b = (const float*)d_in[16];
    const float* bn1_m = (const float*)d_in[17];
    const float* bn1_v = (const float*)d_in[18];
    const float* sh_w  = (const float*)d_in[19];
    const float* sh_b  = (const float*)d_in[20];
    const float* bn2_g = (const float*)d_in[21];
    const float* bn2_b = (const float*)d_in[22];
    const float* bn2_m = (const float*)d_in[23];
    const float* bn2_v = (const float*)d_in[24];
    const float* last_w  = (const float*)d_in[25];
    const float* last_b  = (const float*)d_in[26];
    const float* last2_w = (const float*)d_in[27];
    const float* last2_b = (const float*)d_in[28];
    float* out = (float*)d_out;

    float *p_xres, *p_y, *p_cat, *p_z;
    cudaGetSymbolAddress((void**)&p_xres, g_xres);
    cudaGetSymbolAddress((void**)&p_y, g_y);
    cudaGetSymbolAddress((void**)&p_cat, g_cat);
    cudaGetSymbolAddress((void**)&p_z, g_z);

    // output part 2: sigmoid(classify_logits)
    sigmoid4_kernel<<<(NB * N2 / 4 + 255) / 256, 256>>>(
        (const float4*)logits, (float4*)(out + (size_t)NB * N1), NB * N2 / 4);
    topk_mask_kernel<<<NB, 256>>>(logits);
    zero_gxsq_kernel<<<1, 512>>>();
    // ConvNeXt block
    dwconv_kernel<<<dim3(4, 4, NB), 256>>>(feats4x, dw_w, dw_b);
    lnpw1_kernel<<<(NB * N4) / 256, 256>>>(ln_g, ln_b, pw1_w, pw1_b);
    grn_kernel<<<1, 512>>>();
    block2_kernel<<<(NB * N4) / 256, 256>>>(feats4x, grn_g, grn_b, pw2_w, pw2_b);
    // up branch: conv 32->8 + bn1 @128^2, upsample into cat ch 0..7
    conv3x3_rb_kernel<32, 8><<<dim3(4, 4, NB), 256>>>(p_xres, 32, up_w, up_b,
        bn1_g, bn1_b, bn1_m, bn1_v, 1, p_y, 8, 0, 128, 128);
    upsample2x_kernel<<<(NB * 8 * N2 + 255) / 256, 256>>>(p_y, p_cat, 8, 128, 128, 8, 16, 0);
    // shortcut branch: conv 16->8 + bn2 + relu @256^2 into cat ch 8..15
    conv3x3_rb_kernel<16, 8><<<dim3(8, 8, NB), 256>>>(feats2x, 16, sh_w, sh_b,
        bn2_g, bn2_b, bn2_m, bn2_v, 2, p_cat, 16, 8, 256, 256);
    // last conv 16->4 @256^2
    conv3x3_rb_kernel<16, 4><<<dim3(8, 8, NB), 256>>>(p_cat, 16, last_w, last_b,
        nullptr, nullptr, nullptr, nullptr, 0, p_z, 4, 0, 256, 256);
    // fused upsample + 5x5 conv + sigmoid -> output part 1
    conv5x5up_sig_kernel<<<dim3(16, 16, NB), 256>>>(last2_w, last2_b, out);
}

// round 4
// speedup vs baseline: 1.7962x; 1.1808x over previous
#include <cuda_runtime.h>
#include <math.h>

#define NB 16
#define N4 (128*128)
#define N2 (256*256)
#define N1 (512*512)
#define KTOP 819

// ---------------- scratch (device globals) ----------------
__device__ float g_mask[NB * N4];
__device__ float g_dwout[NB * 32 * N4];
__device__ float g_xh1[NB * N4 * 32];
__device__ float g_gxsq[NB * 32];
__device__ float g_nx[NB * 32];
__device__ float g_xres[NB * 32 * N4];
__device__ float g_y[NB * 8 * N4];
__device__ float g_cat[NB * 16 * N2];
__device__ float g_z[NB * 4 * N2];

__device__ __forceinline__ float sigmoidf_(float x) { return 1.0f / (1.0f + expf(-x)); }

// ---------------- sigmoid (output part 2) ----------------
__global__ void sigmoid4_kernel(const float4* __restrict__ in, float4* __restrict__ out, int n4) {
    int i = blockIdx.x * 256 + threadIdx.x;
    if (i < n4) {
        float4 v = in[i];
        out[i] = make_float4(sigmoidf_(v.x), sigmoidf_(v.y), sigmoidf_(v.z), sigmoidf_(v.w));
    }
}

// ---------------- top-k threshold + mask ----------------
__global__ __launch_bounds__(256) void topk_mask_kernel(const float* __restrict__ logits) {
    int b = blockIdx.x;
    int tid = threadIdx.x;
    unsigned key[64];
    const float* lp = logits + (size_t)b * N2;
#pragma unroll
    for (int i = 0; i < 64; i++) {
        int idx = tid + i * 256;
        int r = idx >> 7, c = idx & 127;
        float v = lp[(r * 2) * 256 + c * 2];
        unsigned u = __float_as_uint(v);
        key[i] = (u & 0x80000000u) ? ~u : (u | 0x80000000u);
    }
    __shared__ int red[8];
    unsigned lo = 0u, hi = 0xFFFFFFFFu;
    while (lo < hi) {
        unsigned d = hi - lo;
        unsigned mid = lo + (d >> 1) + (d & 1u);
        int cnt = 0;
#pragma unroll
        for (int i = 0; i < 64; i++) cnt += (key[i] >= mid) ? 1 : 0;
        for (int off = 16; off; off >>= 1) cnt += __shfl_xor_sync(0xffffffffu, cnt, off);
        if ((tid & 31) == 0) red[tid >> 5] = cnt;
        __syncthreads();
        int total = red[0] + red[1] + red[2] + red[3] + red[4] + red[5] + red[6] + red[7];
        if (total >= KTOP) lo = mid; else hi = mid - 1;
        __syncthreads();
    }
#pragma unroll
    for (int i = 0; i < 64; i++)
        g_mask[b * N4 + tid + i * 256] = (key[i] > lo) ? 1.0f : 0.0f;
}

__global__ void zero_gxsq_kernel() {
    if (threadIdx.x < NB * 32) g_gxsq[threadIdx.x] = 0.0f;
}

// ---------------- depthwise 7x7 conv: channel-parallel, 2x2 px/thread ----------------
// grid (4,4,NB*32), 256 threads, 32x32 output tile per (b,ci).
__global__ __launch_bounds__(256) void dwconv_v2_kernel(
    const float* __restrict__ feats4x, const float* __restrict__ dw_w, const float* __restrict__ dw_b) {
    __shared__ float s_t[38 * 38];
    __shared__ float s_w[49];
    int tid = threadIdx.x;
    int tx = tid & 15, ty = tid >> 4;
    int bc = blockIdx.z;
    int b = bc >> 5, ci = bc & 31;
    int h0 = blockIdx.y * 32, w0 = blockIdx.x * 32;
    if (tid < 49) s_w[tid] = dw_w[ci * 49 + tid];
    const float* ip = feats4x + ((size_t)(b * 32 + ci)) * N4;
    for (int i = tid; i < 38 * 38; i += 256) {
        int r = i / 38, c = i - r * 38;
        int gh = h0 + r - 3, gw = w0 + c - 3;
        s_t[i] = (gh >= 0 && gh < 128 && gw >= 0 && gw < 128) ? ip[gh * 128 + gw] : 0.0f;
    }
    __syncthreads();

    int bty = 2 * ty, btx = 2 * tx;
    float a00 = 0.f, a01 = 0.f, a10 = 0.f, a11 = 0.f;
    float wp[7];
#pragma unroll
    for (int ir = 0; ir < 8; ir++) {
        float t[8];
#pragma unroll
        for (int c = 0; c < 8; c++) t[c] = s_t[(bty + ir) * 38 + btx + c];
        float wr[7];
        if (ir < 7) {
#pragma unroll
            for (int k = 0; k < 7; k++) wr[k] = s_w[ir * 7 + k];
#pragma unroll
            for (int k = 0; k < 7; k++) {
                a00 = fmaf(t[k], wr[k], a00);
                a01 = fmaf(t[k + 1], wr[k], a01);
            }
        }
        if (ir >= 1) {
#pragma unroll
            for (int k = 0; k < 7; k++) {
                a10 = fmaf(t[k], wp[k], a10);
                a11 = fmaf(t[k + 1], wp[k], a11);
            }
        }
#pragma unroll
        for (int k = 0; k < 7; k++) wp[k] = wr[k];
    }
    float bias = dw_b[ci];
    float* op = g_dwout + ((size_t)(b * 32 + ci)) * N4 + (h0 + bty) * 128 + w0 + btx;
    *reinterpret_cast<float2*>(op) = make_float2(a00 + bias, a01 + bias);
    *reinterpret_cast<float2*>(op + 128) = make_float2(a10 + bias, a11 + bias);
}

// ---------------- mask + LN + pw1 + gelu + sumsq ----------------
__global__ __launch_bounds__(256) void lnpw1_kernel(
    const float* __restrict__ ln_g, const float* __restrict__ ln_b,
    const float* __restrict__ pw1_w, const float* __restrict__ pw1_b) {
    __shared__ float s_pw1[1024];
    __shared__ float s_lng[32], s_lnb[32], s_pb[32];
    __shared__ float s_bsum[32];
    int tid = threadIdx.x;
    for (int i = tid; i < 1024; i += 256) s_pw1[i] = pw1_w[i];
    if (tid < 32) { s_lng[tid] = ln_g[tid]; s_lnb[tid] = ln_b[tid]; s_pb[tid] = pw1_b[tid]; s_bsum[tid] = 0.0f; }
    __syncthreads();

    int p = blockIdx.x * 256 + tid;
    int b = p >> 14, sp = p & 16383;
    float v[32];
#pragma unroll
    for (int c = 0; c < 32; c++) v[c] = g_dwout[((size_t)(b * 32 + c)) * N4 + sp];
    float m = g_mask[p];
    float mu = 0.0f;
#pragma unroll
    for (int c = 0; c < 32; c++) { v[c] *= m; mu += v[c]; }
    mu *= (1.0f / 32.0f);
    float var = 0.0f;
#pragma unroll
    for (int c = 0; c < 32; c++) { float d = v[c] - mu; var = fmaf(d, d, var); }
    var *= (1.0f / 32.0f);
    float rs = rsqrtf(var + 1e-6f);
#pragma unroll
    for (int c = 0; c < 32; c++)
        v[c] = ((v[c] - mu) * rs * s_lng[c] + s_lnb[c]) * m;

    float4* dst = reinterpret_cast<float4*>(g_xh1 + (size_t)p * 32);
    const float4* wf4 = reinterpret_cast<const float4*>(s_pw1);
#pragma unroll
    for (int jq = 0; jq < 8; jq++) {
        float y4[4];
#pragma unroll
        for (int u = 0; u < 4; u++) {
            int j = jq * 4 + u;
            float t = s_pb[j];
#pragma unroll
            for (int cq = 0; cq < 8; cq++) {
                float4 w = wf4[j * 8 + cq];
                t = fmaf(v[4 * cq], w.x, t);
                t = fmaf(v[4 * cq + 1], w.y, t);
                t = fmaf(v[4 * cq + 2], w.z, t);
                t = fmaf(v[4 * cq + 3], w.w, t);
            }
            float g = 0.5f * t * (1.0f + erff(t * 0.70710678118654752f));
            y4[u] = g;
            float sq = g * g;
            for (int off = 16; off; off >>= 1) sq += __shfl_xor_sync(0xffffffffu, sq, off);
            if ((tid & 31) == 0) atomicAdd(&s_bsum[j], sq);
        }
        dst[jq] = make_float4(y4[0], y4[1], y4[2], y4[3]);
    }
    __syncthreads();
    if (tid < 32) atomicAdd(&g_gxsq[b * 32 + tid], s_bsum[tid]);
}

// ---------------- GRN stats ----------------
__global__ void grn_kernel() {
    int b = threadIdx.x >> 5;
    int lane = threadIdx.x & 31;
    if (b < NB) {
        float g = sqrtf(g_gxsq[b * 32 + lane]);
        float s = g;
        for (int off = 16; off; off >>= 1) s += __shfl_xor_sync(0xffffffffu, s, off);
        float mean = s * (1.0f / 32.0f);
        g_nx[b * 32 + lane] = g / (mean + 1e-6f);
    }
}

// ---------------- block2: GRN + pw2 + residual ----------------
__global__ __launch_bounds__(256) void block2_kernel(
    const float* __restrict__ feats4x,
    const float* __restrict__ grn_g, const float* __restrict__ grn_b,
    const float* __restrict__ pw2_w, const float* __restrict__ pw2_b) {
    __shared__ float s_pw2[1024];
    __shared__ float s_gg[32], s_gb[32], s_pb[32];
    int tid = threadIdx.x;
    for (int i = tid; i < 1024; i += 256) s_pw2[i] = pw2_w[i];
    if (tid < 32) { s_gg[tid] = grn_g[tid]; s_gb[tid] = grn_b[tid]; s_pb[tid] = pw2_b[tid]; }
    __syncthreads();
    int p = blockIdx.x * 256 + tid;
    int b = p >> 14, sp = p & 16383;
    float t[32];
    const float4* src = reinterpret_cast<const float4*>(g_xh1 + (size_t)p * 32);
#pragma unroll
    for (int q = 0; q < 8; q++) {
        float4 v = src[q];
        t[4 * q] = v.x; t[4 * q + 1] = v.y; t[4 * q + 2] = v.z; t[4 * q + 3] = v.w;
    }
#pragma unroll
    for (int c = 0; c < 32; c++) {
        float nx = g_nx[b * 32 + c];
        t[c] = fmaf(s_gg[c], t[c] * nx, s_gb[c]) + t[c];
    }
    const float4* wf4 = reinterpret_cast<const float4*>(s_pw2);
#pragma unroll
    for (int j = 0; j < 32; j++) {
        float o = s_pb[j];
#pragma unroll
        for (int cq = 0; cq < 8; cq++) {
            float4 w = wf4[j * 8 + cq];
            o = fmaf(t[4 * cq], w.x, o);
            o = fmaf(t[4 * cq + 1], w.y, o);
            o = fmaf(t[4 * cq + 2], w.z, o);
            o = fmaf(t[4 * cq + 3], w.w, o);
        }
        size_t idx = ((size_t)(b * 32 + j)) * N4 + sp;
        g_xres[idx] = feats4x[idx] + o;
    }
}

// ---------------- 3x3 conv v2: 8-channel phases in dynamic shared, 2x2 px/thread ----------------
// 32x32 tile, 256 threads. smem per phase: 8 channels x 34x34.
template <int CIN, int COUT>
__global__ __launch_bounds__(256) void conv3x3_v2_kernel(
    const float* __restrict__ in, int inChTot,
    const float* __restrict__ wgt, const float* __restrict__ bias,
    const float* __restrict__ bn_g, const float* __restrict__ bn_b,
    const float* __restrict__ bn_m, const float* __restrict__ bn_v,
    int mode, float* __restrict__ out, int outChTot, int outChOff, int H, int W) {
    extern __shared__ float s_in[];                 // 8 * 1156 floats
    __shared__ float s_w[COUT * CIN * 12];
    int tid = threadIdx.x;
    int tx = tid & 15, ty = tid >> 4;
    int b = blockIdx.z;
    int h0 = blockIdx.y * 32, w0 = blockIdx.x * 32;
    for (int i = tid; i < COUT * CIN * 12; i += 256) {
        int q = i / 12, k = i - q * 12;
        s_w[i] = (k < 9) ? wgt[q * 9 + k] : 0.0f;
    }
    float acc[COUT][4];
#pragma unroll
    for (int o = 0; o < COUT; o++)
#pragma unroll
        for (int u = 0; u < 4; u++) acc[o][u] = 0.0f;

    int bty = 2 * ty, btx = 2 * tx;
#pragma unroll 1
    for (int phase = 0; phase < CIN / 8; phase++) {
        __syncthreads();   // also orders s_w on first pass; protects s_in reuse after
        const float* bp = in + ((size_t)(b * inChTot + phase * 8)) * H * W;
        for (int i = tid; i < 8 * 1156; i += 256) {
            int ch = i / 1156, j = i - ch * 1156;
            int r = j / 34, c = j - r * 34;
            int gh = h0 + r - 1, gw = w0 + c - 1;
            s_in[i] = (gh >= 0 && gh < H && gw >= 0 && gw < W)
                      ? bp[(size_t)ch * H * W + gh * W + gw] : 0.0f;
        }
        __syncthreads();
#pragma unroll 1
        for (int ci8 = 0; ci8 < 8; ci8++) {
            int ci = phase * 8 + ci8;
            const float* st = s_in + ci8 * 1156;
            float t[16];
#pragma unroll
            for (int r = 0; r < 4; r++) {
                float2 p0 = *reinterpret_cast<const float2*>(st + (bty + r) * 34 + btx);
                float2 p1 = *reinterpret_cast<const float2*>(st + (bty + r) * 34 + btx + 2);
                t[r * 4 + 0] = p0.x; t[r * 4 + 1] = p0.y; t[r * 4 + 2] = p1.x; t[r * 4 + 3] = p1.y;
            }
#pragma unroll
            for (int o = 0; o < COUT; o++) {
                const float* wb = s_w + (o * CIN + ci) * 12;
                float4 wa = *reinterpret_cast<const float4*>(wb);
                float4 wv = *reinterpret_cast<const float4*>(wb + 4);
                float w8 = wb[8];
#pragma unroll
                for (int r = 0; r < 2; r++)
#pragma unroll
                    for (int c = 0; c < 2; c++) {
                        float a = acc[o][r * 2 + c];
                        a = fmaf(t[(r + 0) * 4 + c + 0], wa.x, a);
                        a = fmaf(t[(r + 0) * 4 + c + 1], wa.y, a);
                        a = fmaf(t[(r + 0) * 4 + c + 2], wa.z, a);
                        a = fmaf(t[(r + 1) * 4 + c + 0], wa.w, a);
                        a = fmaf(t[(r + 1) * 4 + c + 1], wv.x, a);
                        a = fmaf(t[(r + 1) * 4 + c + 2], wv.y, a);
                        a = fmaf(t[(r + 2) * 4 + c + 0], wv.z, a);
                        a = fmaf(t[(r + 2) * 4 + c + 1], wv.w, a);
                        a = fmaf(t[(r + 2) * 4 + c + 2], w8, a);
                        acc[o][r * 2 + c] = a;
                    }
            }
        }
    }
#pragma unroll
    for (int o = 0; o < COUT; o++) {
        float bs = bias[o];
        float sc = 1.0f, sh = 0.0f;
        if (mode >= 1) {
            sc = bn_g[o] * rsqrtf(bn_v[o] + 1e-5f);
            sh = bn_b[o] - bn_m[o] * sc;
        }
        float* op = out + ((size_t)(b * outChTot + outChOff + o)) * H * W + (h0 + bty) * W + w0 + btx;
#pragma unroll
        for (int r = 0; r < 2; r++) {
            float r0 = acc[o][r * 2 + 0] + bs;
            float r1 = acc[o][r * 2 + 1] + bs;
            if (mode >= 1) { r0 = fmaf(r0, sc, sh); r1 = fmaf(r1, sc, sh); }
            if (mode == 2) { r0 = fmaxf(r0, 0.0f); r1 = fmaxf(r1, 0.0f); }
            *reinterpret_cast<float2*>(op + r * W) = make_float2(r0, r1);
        }
    }
}

// ---------------- bilinear 2x upsample ----------------
__global__ void upsample2x_kernel(const float* __restrict__ in, float* __restrict__ out,
                                  int Cn, int Hs, int Ws, int inChTot, int outChTot, int outChOff) {
    int gid = blockIdx.x * 256 + threadIdx.x;
    int Wo = Ws * 2, Ho = Hs * 2;
    int total = NB * Cn * Ho * Wo;
    if (gid >= total) return;
    int ox = gid % Wo; int t = gid / Wo;
    int oy = t % Ho; t /= Ho;
    int c = t % Cn; int b = t / Cn;
    float fy = oy * 0.5f - 0.25f, fx = ox * 0.5f - 0.25f;
    int y0 = (int)floorf(fy), x0 = (int)floorf(fx);
    float wy = fy - (float)y0, wx = fx - (float)x0;
    int y0c = y0 < 0 ? 0 : y0;
    int y1c = (y0 + 1) > (Hs - 1) ? (Hs - 1) : (y0 + 1);
    int x0c = x0 < 0 ? 0 : x0;
    int x1c = (x0 + 1) > (Ws - 1) ? (Ws - 1) : (x0 + 1);
    const float* ip = in + ((size_t)(b * inChTot + c)) * Hs * Ws;
    float v00 = ip[y0c * Ws + x0c], v01 = ip[y0c * Ws + x1c];
    float v10 = ip[y1c * Ws + x0c], v11 = ip[y1c * Ws + x1c];
    float v = (1.0f - wy) * ((1.0f - wx) * v00 + wx * v01) + wy * ((1.0f - wx) * v10 + wx * v11);
    out[((size_t)(b * outChTot + outChOff + c)) * Ho * Wo + oy * Wo + ox] = v;
}

// ---------------- fused up2x(z) -> conv5x5 -> sigmoid ----------------
__global__ __launch_bounds__(256) void conv5x5up_sig_kernel(
    const float* __restrict__ w25, const float* __restrict__ bias, float* __restrict__ out) {
    __shared__ float s_w[4 * 28];
    __shared__ float s_uz[36 * 36];
    int tid = threadIdx.x;
    int tx = tid & 15, ty = tid >> 4;
    int b = blockIdx.z, h0 = blockIdx.y * 32, w0 = blockIdx.x * 32;
    if (tid < 112) {
        int ch = tid / 28, k = tid % 28;
        s_w[tid] = (k < 25) ? w25[ch * 25 + k] : 0.0f;
    }
    float acc[4] = {0.f, 0.f, 0.f, 0.f};
    int bty = 2 * ty, btx = 2 * tx;
    for (int ch = 0; ch < 4; ch++) {
        __syncthreads();
        const float* zp = g_z + ((size_t)(b * 4 + ch)) * N2;
        for (int i = tid; i < 36 * 36; i += 256) {
            int r = i / 36, c = i - r * 36;
            int oy = h0 - 2 + r, ox = w0 - 2 + c;
            float v = 0.0f;
            if (oy >= 0 && oy < 512 && ox >= 0 && ox < 512) {
                float fy = oy * 0.5f - 0.25f, fx = ox * 0.5f - 0.25f;
                int y0 = (int)floorf(fy), x0 = (int)floorf(fx);
                float wy = fy - (float)y0, wx = fx - (float)x0;
                int y0c = y0 < 0 ? 0 : y0;
                int y1c = (y0 + 1) > 255 ? 255 : (y0 + 1);
                int x0c = x0 < 0 ? 0 : x0;
                int x1c = (x0 + 1) > 255 ? 255 : (x0 + 1);
                float v00 = zp[y0c * 256 + x0c], v01 = zp[y0c * 256 + x1c];
                float v10 = zp[y1c * 256 + x0c], v11 = zp[y1c * 256 + x1c];
                v = (1.0f - wy) * ((1.0f - wx) * v00 + wx * v01)
                  + wy * ((1.0f - wx) * v10 + wx * v11);
            }
            s_uz[i] = v;
        }
        __syncthreads();
        float t[36];
#pragma unroll
        for (int r = 0; r < 6; r++)
#pragma unroll
            for (int c = 0; c < 6; c++)
                t[r * 6 + c] = s_uz[(bty + r) * 36 + btx + c];
        const float* wb = s_w + ch * 28;
#pragma unroll
        for (int r = 0; r < 2; r++)
#pragma unroll
            for (int c = 0; c < 2; c++) {
                float a = acc[r * 2 + c];
#pragma unroll
                for (int kh = 0; kh < 5; kh++)
#pragma unroll
                    for (int kw = 0; kw < 5; kw++)
                        a = fmaf(t[(r + kh) * 6 + c + kw], wb[kh * 5 + kw], a);
                acc[r * 2 + c] = a;
            }
    }
    float bs = bias[0];
    float* op = out + (size_t)b * N1 + (h0 + bty) * 512 + w0 + btx;
#pragma unroll
    for (int r = 0; r < 2; r++) {
        float r0 = sigmoidf_(acc[r * 2 + 0] + bs);
        float r1 = sigmoidf_(acc[r * 2 + 1] + bs);
        *reinterpret_cast<float2*>(op + r * 512) = make_float2(r0, r1);
    }
}

// ---------------- launcher ----------------
extern "C" void kernel_launch(void* const* d_in, const int* in_sizes, int n_in,
                              void* d_out, int out_size) {
    const float* feats4x = (const float*)d_in[0];
    const float* feats2x = (const float*)d_in[1];
    const float* logits  = (const float*)d_in[2];
    const float* dw_w  = (const float*)d_in[3];
    const float* dw_b  = (const float*)d_in[4];
    const float* ln_g  = (const float*)d_in[5];
    const float* ln_b  = (const float*)d_in[6];
    const float* pw1_w = (const float*)d_in[7];
    const float* pw1_b = (const float*)d_in[8];
    const float* grn_g = (const float*)d_in[9];
    const float* grn_b = (const float*)d_in[10];
    const float* pw2_w = (const float*)d_in[11];
    const float* pw2_b = (const float*)d_in[12];
    const float* up_w  = (const float*)d_in[13];
    const float* up_b  = (const float*)d_in[14];
    const float* bn1_g = (const float*)d_in[15];
    const float* bn1_b = (const float*)d_in[16];
    const float* bn1_m = (const float*)d_in[17];
    const float* bn1_v = (const float*)d_in[18];
    const float* sh_w  = (const float*)d_in[19];
    const float* sh_b  = (const float*)d_in[20];
    const float* bn2_g = (const float*)d_in[21];
    const float* bn2_b = (const float*)d_in[22];
    const float* bn2_m = (const float*)d_in[23];
    const float* bn2_v = (const float*)d_in[24];
    const float* last_w  = (const float*)d_in[25];
    const float* last_b  = (const float*)d_in[26];
    const float* last2_w = (const float*)d_in[27];
    const float* last2_b = (const float*)d_in[28];
    float* out = (float*)d_out;

    float *p_xres, *p_y, *p_cat, *p_z;
    cudaGetSymbolAddress((void**)&p_xres, g_xres);
    cudaGetSymbolAddress((void**)&p_y, g_y);
    cudaGetSymbolAddress((void**)&p_cat, g_cat);
    cudaGetSymbolAddress((void**)&p_z, g_z);

    const int DSM = 8 * 1156 * 4;   // 36992 B dynamic shared for conv3x3_v2
    static bool attr_done = false;
    if (!attr_done) {
        cudaFuncSetAttribute(conv3x3_v2_kernel<32, 8>, cudaFuncAttributeMaxDynamicSharedMemorySize, DSM);
        cudaFuncSetAttribute(conv3x3_v2_kernel<16, 8>, cudaFuncAttributeMaxDynamicSharedMemorySize, DSM);
        cudaFuncSetAttribute(conv3x3_v2_kernel<16, 4>, cudaFuncAttributeMaxDynamicSharedMemorySize, DSM);
        attr_done = true;
    }

    sigmoid4_kernel<<<(NB * N2 / 4 + 255) / 256, 256>>>(
        (const float4*)logits, (float4*)(out + (size_t)NB * N1), NB * N2 / 4);
    topk_mask_kernel<<<NB, 256>>>(logits);
    zero_gxsq_kernel<<<1, 512>>>();
    // ConvNeXt block
    dwconv_v2_kernel<<<dim3(4, 4, NB * 32), 256>>>(feats4x, dw_w, dw_b);
    lnpw1_kernel<<<(NB * N4) / 256, 256>>>(ln_g, ln_b, pw1_w, pw1_b);
    grn_kernel<<<1, 512>>>();
    block2_kernel<<<(NB * N4) / 256, 256>>>(feats4x, grn_g, grn_b, pw2_w, pw2_b);
    // up branch
    conv3x3_v2_kernel<32, 8><<<dim3(4, 4, NB), 256, DSM>>>(p_xres, 32, up_w, up_b,
        bn1_g, bn1_b, bn1_m, bn1_v, 1, p_y, 8, 0, 128, 128);
    upsample2x_kernel<<<(NB * 8 * N2 + 255) / 256, 256>>>(p_y, p_cat, 8, 128, 128, 8, 16, 0);
    // shortcut branch
    conv3x3_v2_kernel<16, 8><<<dim3(8, 8, NB), 256, DSM>>>(feats2x, 16, sh_w, sh_b,
        bn2_g, bn2_b, bn2_m, bn2_v, 2, p_cat, 16, 8, 256, 256);
    // last conv
    conv3x3_v2_kernel<16, 4><<<dim3(8, 8, NB), 256, DSM>>>(p_cat, 16, last_w, last_b,
        nullptr, nullptr, nullptr, nullptr, 0, p_z, 4, 0, 256, 256);
    // fused upsample + 5x5 + sigmoid
    conv5x5up_sig_kernel<<<dim3(16, 16, NB), 256>>>(last2_w, last2_b, out);
}

// round 5
// speedup vs baseline: 1.9874x; 1.1065x over previous
#include <cuda_runtime.h>
#include <math.h>

#define NB 16
#define N4 (128*128)
#define N2 (256*256)
#define N1 (512*512)
#define KTOP 819

// ---------------- scratch (device globals) ----------------
__device__ float g_mask[NB * N4];
__device__ float g_dwout[NB * 32 * N4];
__device__ float g_xh1[NB * N4 * 32];
__device__ float g_gxsq[NB * 32];
__device__ float g_nx[NB * 32];
__device__ float g_xres[NB * 32 * N4];
__device__ float g_y[NB * 8 * N4];
__device__ float g_cat[NB * 16 * N2];
__device__ float g_z[NB * 4 * N2];

__device__ __forceinline__ float sigmoidf_(float x) { return 1.0f / (1.0f + expf(-x)); }

// ---------------- sigmoid (output part 2) ----------------
__global__ void sigmoid4_kernel(const float4* __restrict__ in, float4* __restrict__ out, int n4) {
    int i = blockIdx.x * 256 + threadIdx.x;
    if (i < n4) {
        float4 v = in[i];
        out[i] = make_float4(sigmoidf_(v.x), sigmoidf_(v.y), sigmoidf_(v.z), sigmoidf_(v.w));
    }
}

// ---------------- top-k threshold + mask ----------------
__global__ __launch_bounds__(256) void topk_mask_kernel(const float* __restrict__ logits) {
    int b = blockIdx.x;
    int tid = threadIdx.x;
    unsigned key[64];
    const float* lp = logits + (size_t)b * N2;
#pragma unroll
    for (int i = 0; i < 64; i++) {
        int idx = tid + i * 256;
        int r = idx >> 7, c = idx & 127;
        float v = lp[(r * 2) * 256 + c * 2];
        unsigned u = __float_as_uint(v);
        key[i] = (u & 0x80000000u) ? ~u : (u | 0x80000000u);
    }
    __shared__ int red[8];
    unsigned lo = 0u, hi = 0xFFFFFFFFu;
    while (lo < hi) {
        unsigned d = hi - lo;
        unsigned mid = lo + (d >> 1) + (d & 1u);
        int cnt = 0;
#pragma unroll
        for (int i = 0; i < 64; i++) cnt += (key[i] >= mid) ? 1 : 0;
        for (int off = 16; off; off >>= 1) cnt += __shfl_xor_sync(0xffffffffu, cnt, off);
        if ((tid & 31) == 0) red[tid >> 5] = cnt;
        __syncthreads();
        int total = red[0] + red[1] + red[2] + red[3] + red[4] + red[5] + red[6] + red[7];
        if (total >= KTOP) lo = mid; else hi = mid - 1;
        __syncthreads();
    }
#pragma unroll
    for (int i = 0; i < 64; i++)
        g_mask[b * N4 + tid + i * 256] = (key[i] > lo) ? 1.0f : 0.0f;
}

__global__ void zero_gxsq_kernel() {
    if (threadIdx.x < NB * 32) g_gxsq[threadIdx.x] = 0.0f;
}

// ---------------- depthwise 7x7 conv v3: 4x2 px/thread, weights in registers ----------------
// tile 32 wide x 64 tall; grid (4, 2, NB*32) = 4096 blocks.
__global__ __launch_bounds__(256) void dwconv_v3_kernel(
    const float* __restrict__ feats4x, const float* __restrict__ dw_w, const float* __restrict__ dw_b) {
    __shared__ float s_t[70 * 38];
    __shared__ float s_w[49];
    int tid = threadIdx.x;
    int tx = tid & 15, ty = tid >> 4;
    int bc = blockIdx.z;
    int b = bc >> 5, ci = bc & 31;
    int h0 = blockIdx.y * 64, w0 = blockIdx.x * 32;
    if (tid < 49) s_w[tid] = dw_w[ci * 49 + tid];
    const float* ip = feats4x + ((size_t)(b * 32 + ci)) * N4;
    for (int i = tid; i < 70 * 38; i += 256) {
        int r = i / 38, c = i - r * 38;
        int gh = h0 + r - 3, gw = w0 + c - 3;
        s_t[i] = (gh >= 0 && gh < 128 && gw >= 0 && gw < 128) ? ip[gh * 128 + gw] : 0.0f;
    }
    __syncthreads();

    float w[49];
#pragma unroll
    for (int k = 0; k < 49; k++) w[k] = s_w[k];

    int bty = 4 * ty, btx = 2 * tx;
    float a[4][2];
#pragma unroll
    for (int r = 0; r < 4; r++) { a[r][0] = 0.f; a[r][1] = 0.f; }

#pragma unroll
    for (int ir = 0; ir < 10; ir++) {
        float t[8];
        const float* row = s_t + (bty + ir) * 38 + btx;
#pragma unroll
        for (int q = 0; q < 4; q++) {
            float2 p = *reinterpret_cast<const float2*>(row + 2 * q);
            t[2 * q] = p.x; t[2 * q + 1] = p.y;
        }
#pragma unroll
        for (int kh = 0; kh < 7; kh++) {
            int r = ir - kh;
            if (r >= 0 && r < 4) {
#pragma unroll
                for (int kw = 0; kw < 7; kw++) {
                    a[r][0] = fmaf(t[kw], w[kh * 7 + kw], a[r][0]);
                    a[r][1] = fmaf(t[kw + 1], w[kh * 7 + kw], a[r][1]);
                }
            }
        }
    }
    float bias = dw_b[ci];
    float* op = g_dwout + ((size_t)(b * 32 + ci)) * N4 + (h0 + bty) * 128 + w0 + btx;
#pragma unroll
    for (int r = 0; r < 4; r++)
        *reinterpret_cast<float2*>(op + r * 128) = make_float2(a[r][0] + bias, a[r][1] + bias);
}

// ---------------- mask + LN + pw1 + gelu + sumsq ----------------
__global__ __launch_bounds__(256) void lnpw1_kernel(
    const float* __restrict__ ln_g, const float* __restrict__ ln_b,
    const float* __restrict__ pw1_w, const float* __restrict__ pw1_b) {
    __shared__ float s_pw1[1024];
    __shared__ float s_lng[32], s_lnb[32], s_pb[32];
    __shared__ float s_bsum[32];
    int tid = threadIdx.x;
    for (int i = tid; i < 1024; i += 256) s_pw1[i] = pw1_w[i];
    if (tid < 32) { s_lng[tid] = ln_g[tid]; s_lnb[tid] = ln_b[tid]; s_pb[tid] = pw1_b[tid]; s_bsum[tid] = 0.0f; }
    __syncthreads();

    int p = blockIdx.x * 256 + tid;
    int b = p >> 14, sp = p & 16383;
    float v[32];
#pragma unroll
    for (int c = 0; c < 32; c++) v[c] = g_dwout[((size_t)(b * 32 + c)) * N4 + sp];
    float m = g_mask[p];
    float mu = 0.0f;
#pragma unroll
    for (int c = 0; c < 32; c++) { v[c] *= m; mu += v[c]; }
    mu *= (1.0f / 32.0f);
    float var = 0.0f;
#pragma unroll
    for (int c = 0; c < 32; c++) { float d = v[c] - mu; var = fmaf(d, d, var); }
    var *= (1.0f / 32.0f);
    float rs = rsqrtf(var + 1e-6f);
#pragma unroll
    for (int c = 0; c < 32; c++)
        v[c] = ((v[c] - mu) * rs * s_lng[c] + s_lnb[c]) * m;

    float4* dst = reinterpret_cast<float4*>(g_xh1 + (size_t)p * 32);
    const float4* wf4 = reinterpret_cast<const float4*>(s_pw1);
#pragma unroll
    for (int jq = 0; jq < 8; jq++) {
        float y4[4];
#pragma unroll
        for (int u = 0; u < 4; u++) {
            int j = jq * 4 + u;
            float t = s_pb[j];
#pragma unroll
            for (int cq = 0; cq < 8; cq++) {
                float4 w = wf4[j * 8 + cq];
                t = fmaf(v[4 * cq], w.x, t);
                t = fmaf(v[4 * cq + 1], w.y, t);
                t = fmaf(v[4 * cq + 2], w.z, t);
                t = fmaf(v[4 * cq + 3], w.w, t);
            }
            float g = 0.5f * t * (1.0f + erff(t * 0.70710678118654752f));
            y4[u] = g;
            float sq = g * g;
            for (int off = 16; off; off >>= 1) sq += __shfl_xor_sync(0xffffffffu, sq, off);
            if ((tid & 31) == 0) atomicAdd(&s_bsum[j], sq);
        }
        dst[jq] = make_float4(y4[0], y4[1], y4[2], y4[3]);
    }
    __syncthreads();
    if (tid < 32) atomicAdd(&g_gxsq[b * 32 + tid], s_bsum[tid]);
}

// ---------------- GRN stats ----------------
__global__ void grn_kernel() {
    int b = threadIdx.x >> 5;
    int lane = threadIdx.x & 31;
    if (b < NB) {
        float g = sqrtf(g_gxsq[b * 32 + lane]);
        float s = g;
        for (int off = 16; off; off >>= 1) s += __shfl_xor_sync(0xffffffffu, s, off);
        float mean = s * (1.0f / 32.0f);
        g_nx[b * 32 + lane] = g / (mean + 1e-6f);
    }
}

// ---------------- block2: GRN + pw2 + residual ----------------
__global__ __launch_bounds__(256) void block2_kernel(
    const float* __restrict__ feats4x,
    const float* __restrict__ grn_g, const float* __restrict__ grn_b,
    const float* __restrict__ pw2_w, const float* __restrict__ pw2_b) {
    __shared__ float s_pw2[1024];
    __shared__ float s_gg[32], s_gb[32], s_pb[32];
    int tid = threadIdx.x;
    for (int i = tid; i < 1024; i += 256) s_pw2[i] = pw2_w[i];
    if (tid < 32) { s_gg[tid] = grn_g[tid]; s_gb[tid] = grn_b[tid]; s_pb[tid] = pw2_b[tid]; }
    __syncthreads();
    int p = blockIdx.x * 256 + tid;
    int b = p >> 14, sp = p & 16383;
    float t[32];
    const float4* src = reinterpret_cast<const float4*>(g_xh1 + (size_t)p * 32);
#pragma unroll
    for (int q = 0; q < 8; q++) {
        float4 v = src[q];
        t[4 * q] = v.x; t[4 * q + 1] = v.y; t[4 * q + 2] = v.z; t[4 * q + 3] = v.w;
    }
#pragma unroll
    for (int c = 0; c < 32; c++) {
        float nx = g_nx[b * 32 + c];
        t[c] = fmaf(s_gg[c], t[c] * nx, s_gb[c]) + t[c];
    }
    const float4* wf4 = reinterpret_cast<const float4*>(s_pw2);
#pragma unroll
    for (int j = 0; j < 32; j++) {
        float o = s_pb[j];
#pragma unroll
        for (int cq = 0; cq < 8; cq++) {
            float4 w = wf4[j * 8 + cq];
            o = fmaf(t[4 * cq], w.x, o);
            o = fmaf(t[4 * cq + 1], w.y, o);
            o = fmaf(t[4 * cq + 2], w.z, o);
            o = fmaf(t[4 * cq + 3], w.w, o);
        }
        size_t idx = ((size_t)(b * 32 + j)) * N4 + sp;
        g_xres[idx] = feats4x[idx] + o;
    }
}

// ---------------- 3x3 conv: 8-channel phases, tile 32 x TH, R rows/thread ----------------
template <int CIN, int COUT, int TH>
__global__ __launch_bounds__(256) void conv3x3_v3_kernel(
    const float* __restrict__ in, int inChTot,
    const float* __restrict__ wgt, const float* __restrict__ bias,
    const float* __restrict__ bn_g, const float* __restrict__ bn_b,
    const float* __restrict__ bn_m, const float* __restrict__ bn_v,
    int mode, float* __restrict__ out, int outChTot, int outChOff, int H, int W) {
    constexpr int R = TH / 16;                     // rows per thread (1 or 2)
    constexpr int CH_STRIDE = (TH + 2) * 34;
    extern __shared__ float s_in[];                // 8 * CH_STRIDE floats
    __shared__ float s_w[COUT * CIN * 12];
    int tid = threadIdx.x;
    int tx = tid & 15, ty = tid >> 4;
    int b = blockIdx.z;
    int h0 = blockIdx.y * TH, w0 = blockIdx.x * 32;
    for (int i = tid; i < COUT * CIN * 12; i += 256) {
        int q = i / 12, k = i - q * 12;
        s_w[i] = (k < 9) ? wgt[q * 9 + k] : 0.0f;
    }
    float acc[COUT][R * 2];
#pragma unroll
    for (int o = 0; o < COUT; o++)
#pragma unroll
        for (int u = 0; u < R * 2; u++) acc[o][u] = 0.0f;

    int bty = R * ty, btx = 2 * tx;
#pragma unroll 1
    for (int phase = 0; phase < CIN / 8; phase++) {
        __syncthreads();
        const float* bp = in + ((size_t)(b * inChTot + phase * 8)) * H * W;
        for (int i = tid; i < 8 * CH_STRIDE; i += 256) {
            int ch = i / CH_STRIDE, j = i - ch * CH_STRIDE;
            int r = j / 34, c = j - r * 34;
            int gh = h0 + r - 1, gw = w0 + c - 1;
            s_in[i] = (gh >= 0 && gh < H && gw >= 0 && gw < W)
                      ? bp[(size_t)ch * H * W + gh * W + gw] : 0.0f;
        }
        __syncthreads();
#pragma unroll 1
        for (int ci8 = 0; ci8 < 8; ci8++) {
            int ci = phase * 8 + ci8;
            const float* st = s_in + ci8 * CH_STRIDE;
            float t[(R + 2) * 4];
#pragma unroll
            for (int r = 0; r < R + 2; r++) {
                float2 p0 = *reinterpret_cast<const float2*>(st + (bty + r) * 34 + btx);
                float2 p1 = *reinterpret_cast<const float2*>(st + (bty + r) * 34 + btx + 2);
                t[r * 4 + 0] = p0.x; t[r * 4 + 1] = p0.y; t[r * 4 + 2] = p1.x; t[r * 4 + 3] = p1.y;
            }
#pragma unroll
            for (int o = 0; o < COUT; o++) {
                const float* wb = s_w + (o * CIN + ci) * 12;
                float4 wa = *reinterpret_cast<const float4*>(wb);
                float4 wv = *reinterpret_cast<const float4*>(wb + 4);
                float w8 = wb[8];
#pragma unroll
                for (int r = 0; r < R; r++)
#pragma unroll
                    for (int c = 0; c < 2; c++) {
                        float a = acc[o][r * 2 + c];
                        a = fmaf(t[(r + 0) * 4 + c + 0], wa.x, a);
                        a = fmaf(t[(r + 0) * 4 + c + 1], wa.y, a);
                        a = fmaf(t[(r + 0) * 4 + c + 2], wa.z, a);
                        a = fmaf(t[(r + 1) * 4 + c + 0], wa.w, a);
                        a = fmaf(t[(r + 1) * 4 + c + 1], wv.x, a);
                        a = fmaf(t[(r + 1) * 4 + c + 2], wv.y, a);
                        a = fmaf(t[(r + 2) * 4 + c + 0], wv.z, a);
                        a = fmaf(t[(r + 2) * 4 + c + 1], wv.w, a);
                        a = fmaf(t[(r + 2) * 4 + c + 2], w8, a);
                        acc[o][r * 2 + c] = a;
                    }
            }
        }
    }
#pragma unroll
    for (int o = 0; o < COUT; o++) {
        float bs = bias[o];
        float sc = 1.0f, sh = 0.0f;
        if (mode >= 1) {
            sc = bn_g[o] * rsqrtf(bn_v[o] + 1e-5f);
            sh = bn_b[o] - bn_m[o] * sc;
        }
        float* op = out + ((size_t)(b * outChTot + outChOff + o)) * H * W + (h0 + bty) * W + w0 + btx;
#pragma unroll
        for (int r = 0; r < R; r++) {
            float r0 = acc[o][r * 2 + 0] + bs;
            float r1 = acc[o][r * 2 + 1] + bs;
            if (mode >= 1) { r0 = fmaf(r0, sc, sh); r1 = fmaf(r1, sc, sh); }
            if (mode == 2) { r0 = fmaxf(r0, 0.0f); r1 = fmaxf(r1, 0.0f); }
            *reinterpret_cast<float2*>(op + r * W) = make_float2(r0, r1);
        }
    }
}

// ---------------- conv_last fused: [up2x(y) | cat ch8-15] -> 3x3 conv 16->4 @256^2 ----------------
// grid (8,8,NB), 256 threads, 32x32 tile, 2x2 px/thread.
__global__ __launch_bounds__(256) void conv_last_fused_kernel(
    const float* __restrict__ wgt, const float* __restrict__ bias) {
    __shared__ float s_y8[8 * 324];                // 18x18 per channel of y
    __shared__ float s_w[4 * 16 * 12];
    extern __shared__ float s_in[];                // 8 * 1156
    int tid = threadIdx.x;
    int tx = tid & 15, ty = tid >> 4;
    int b = blockIdx.z;
    int h0 = blockIdx.y * 32, w0 = blockIdx.x * 32;
    for (int i = tid; i < 4 * 16 * 12; i += 256) {
        int q = i / 12, k = i - q * 12;
        s_w[i] = (k < 9) ? wgt[q * 9 + k] : 0.0f;
    }
    int ybase = h0 / 2 - 1, xbase = w0 / 2 - 1;
    // stage y tiles (18x18, clamped) for ch 0..7
    for (int i = tid; i < 8 * 324; i += 256) {
        int ch = i / 324, j = i - ch * 324;
        int r = j / 18, c = j - r * 18;
        int gy = ybase + r; gy = gy < 0 ? 0 : (gy > 127 ? 127 : gy);
        int gx = xbase + c; gx = gx < 0 ? 0 : (gx > 127 ? 127 : gx);
        s_y8[i] = g_y[((size_t)(b * 8 + ch)) * N4 + gy * 128 + gx];
    }
    __syncthreads();
    // build upsampled 34x34 tiles for ch 0..7
    for (int i = tid; i < 8 * 1156; i += 256) {
        int ch = i / 1156, j = i - ch * 1156;
        int r = j / 34, c = j - r * 34;
        int oy = h0 - 1 + r, ox = w0 - 1 + c;
        float v = 0.0f;
        if (oy >= 0 && oy < 256 && ox >= 0 && ox < 256) {
            int my = oy >> 1, mx = ox >> 1;
            int oyo = oy & 1, oxo = ox & 1;
            int gy0 = oyo ? my : my - 1;  int gy1 = oyo ? my + 1 : my;
            float wy1 = oyo ? 0.25f : 0.75f;
            int gx0 = oxo ? mx : mx - 1;  int gx1 = oxo ? mx + 1 : mx;
            float wx1 = oxo ? 0.25f : 0.75f;
            gy0 = gy0 < 0 ? 0 : gy0;  gy1 = gy1 > 127 ? 127 : gy1;
            gx0 = gx0 < 0 ? 0 : gx0;  gx1 = gx1 > 127 ? 127 : gx1;
            int ly0 = gy0 - ybase, ly1 = gy1 - ybase;
            int lx0 = gx0 - xbase, lx1 = gx1 - xbase;
            const float* yp = s_y8 + ch * 324;
            float v00 = yp[ly0 * 18 + lx0], v01 = yp[ly0 * 18 + lx1];
            float v10 = yp[ly1 * 18 + lx0], v11 = yp[ly1 * 18 + lx1];
            v = (1.0f - wy1) * ((1.0f - wx1) * v00 + wx1 * v01)
              + wy1 * ((1.0f - wx1) * v10 + wx1 * v11);
        }
        s_in[i] = v;
    }
    __syncthreads();

    int bty = 2 * ty, btx = 2 * tx;
    float acc[4][4];
#pragma unroll
    for (int o = 0; o < 4; o++)
#pragma unroll
        for (int u = 0; u < 4; u++) acc[o][u] = 0.0f;

#pragma unroll 1
    for (int phase = 0; phase < 2; phase++) {
        if (phase == 1) {
            __syncthreads();
            const float* bp = g_cat + ((size_t)(b * 16 + 8)) * N2;
            for (int i = tid; i < 8 * 1156; i += 256) {
                int ch = i / 1156, j = i - ch * 1156;
                int r = j / 34, c = j - r * 34;
                int gh = h0 + r - 1, gw = w0 + c - 1;
                s_in[i] = (gh >= 0 && gh < 256 && gw >= 0 && gw < 256)
                          ? bp[(size_t)ch * N2 + gh * 256 + gw] : 0.0f;
            }
            __syncthreads();
        }
#pragma unroll 1
        for (int ci8 = 0; ci8 < 8; ci8++) {
            int ci = phase * 8 + ci8;
            const float* st = s_in + ci8 * 1156;
            float t[16];
#pragma unroll
            for (int r = 0; r < 4; r++) {
                float2 p0 = *reinterpret_cast<const float2*>(st + (bty + r) * 34 + btx);
                float2 p1 = *reinterpret_cast<const float2*>(st + (bty + r) * 34 + btx + 2);
                t[r * 4 + 0] = p0.x; t[r * 4 + 1] = p0.y; t[r * 4 + 2] = p1.x; t[r * 4 + 3] = p1.y;
            }
#pragma unroll
            for (int o = 0; o < 4; o++) {
                const float* wb = s_w + (o * 16 + ci) * 12;
                float4 wa = *reinterpret_cast<const float4*>(wb);
                float4 wv = *reinterpret_cast<const float4*>(wb + 4);
                float w8 = wb[8];
#pragma unroll
                for (int r = 0; r < 2; r++)
#pragma unroll
                    for (int c = 0; c < 2; c++) {
                        float a = acc[o][r * 2 + c];
                        a = fmaf(t[(r + 0) * 4 + c + 0], wa.x, a);
                        a = fmaf(t[(r + 0) * 4 + c + 1], wa.y, a);
                        a = fmaf(t[(r + 0) * 4 + c + 2], wa.z, a);
                        a = fmaf(t[(r + 1) * 4 + c + 0], wa.w, a);
                        a = fmaf(t[(r + 1) * 4 + c + 1], wv.x, a);
                        a = fmaf(t[(r + 1) * 4 + c + 2], wv.y, a);
                        a = fmaf(t[(r + 2) * 4 + c + 0], wv.z, a);
                        a = fmaf(t[(r + 2) * 4 + c + 1], wv.w, a);
                        a = fmaf(t[(r + 2) * 4 + c + 2], w8, a);
                        acc[o][r * 2 + c] = a;
                    }
            }
        }
    }
#pragma unroll
    for (int o = 0; o < 4; o++) {
        float bs = bias[o];
        float* op = g_z + ((size_t)(b * 4 + o)) * N2 + (h0 + bty) * 256 + w0 + btx;
#pragma unroll
        for (int r = 0; r < 2; r++)
            *reinterpret_cast<float2*>(op + r * 256) =
                make_float2(acc[o][r * 2 + 0] + bs, acc[o][r * 2 + 1] + bs);
    }
}

// ---------------- fused up2x(z) -> conv5x5 -> sigmoid ----------------
__global__ __launch_bounds__(256) void conv5x5up_sig_kernel(
    const float* __restrict__ w25, const float* __restrict__ bias, float* __restrict__ out) {
    __shared__ float s_w[4 * 28];
    __shared__ float s_uz[36 * 36];
    int tid = threadIdx.x;
    int tx = tid & 15, ty = tid >> 4;
    int b = blockIdx.z, h0 = blockIdx.y * 32, w0 = blockIdx.x * 32;
    if (tid < 112) {
        int ch = tid / 28, k = tid % 28;
        s_w[tid] = (k < 25) ? w25[ch * 25 + k] : 0.0f;
    }
    float acc[4] = {0.f, 0.f, 0.f, 0.f};
    int bty = 2 * ty, btx = 2 * tx;
    for (int ch = 0; ch < 4; ch++) {
        __syncthreads();
        const float* zp = g_z + ((size_t)(b * 4 + ch)) * N2;
        for (int i = tid; i < 36 * 36; i += 256) {
            int r = i / 36, c = i - r * 36;
            int oy = h0 - 2 + r, ox = w0 - 2 + c;
            float v = 0.0f;
            if (oy >= 0 && oy < 512 && ox >= 0 && ox < 512) {
                float fy = oy * 0.5f - 0.25f, fx = ox * 0.5f - 0.25f;
                int y0 = (int)floorf(fy), x0 = (int)floorf(fx);
                float wy = fy - (float)y0, wx = fx - (float)x0;
                int y0c = y0 < 0 ? 0 : y0;
                int y1c = (y0 + 1) > 255 ? 255 : (y0 + 1);
                int x0c = x0 < 0 ? 0 : x0;
                int x1c = (x0 + 1) > 255 ? 255 : (x0 + 1);
                float v00 = zp[y0c * 256 + x0c], v01 = zp[y0c * 256 + x1c];
                float v10 = zp[y1c * 256 + x0c], v11 = zp[y1c * 256 + x1c];
                v = (1.0f - wy) * ((1.0f - wx) * v00 + wx * v01)
                  + wy * ((1.0f - wx) * v10 + wx * v11);
            }
            s_uz[i] = v;
        }
        __syncthreads();
        float t[36];
#pragma unroll
        for (int r = 0; r < 6; r++)
#pragma unroll
            for (int c = 0; c < 6; c++)
                t[r * 6 + c] = s_uz[(bty + r) * 36 + btx + c];
        const float* wb = s_w + ch * 28;
#pragma unroll
        for (int r = 0; r < 2; r++)
#pragma unroll
            for (int c = 0; c < 2; c++) {
                float a = acc[r * 2 + c];
#pragma unroll
                for (int kh = 0; kh < 5; kh++)
#pragma unroll
                    for (int kw = 0; kw < 5; kw++)
                        a = fmaf(t[(r + kh) * 6 + c + kw], wb[kh * 5 + kw], a);
                acc[r * 2 + c] = a;
            }
    }
    float bs = bias[0];
    float* op = out + (size_t)b * N1 + (h0 + bty) * 512 + w0 + btx;
#pragma unroll
    for (int r = 0; r < 2; r++) {
        float r0 = sigmoidf_(acc[r * 2 + 0] + bs);
        float r1 = sigmoidf_(acc[r * 2 + 1] + bs);
        *reinterpret_cast<float2*>(op + r * 512) = make_float2(r0, r1);
    }
}

// ---------------- launcher ----------------
extern "C" void kernel_launch(void* const* d_in, const int* in_sizes, int n_in,
                              void* d_out, int out_size) {
    const float* feats4x = (const float*)d_in[0];
    const float* feats2x = (const float*)d_in[1];
    const float* logits  = (const float*)d_in[2];
    const float* dw_w  = (const float*)d_in[3];
    const float* dw_b  = (const float*)d_in[4];
    const float* ln_g  = (const float*)d_in[5];
    const float* ln_b  = (const float*)d_in[6];
    const float* pw1_w = (const float*)d_in[7];
    const float* pw1_b = (const float*)d_in[8];
    const float* grn_g = (const float*)d_in[9];
    const float* grn_b = (const float*)d_in[10];
    const float* pw2_w = (const float*)d_in[11];
    const float* pw2_b = (const float*)d_in[12];
    const float* up_w  = (const float*)d_in[13];
    const float* up_b  = (const float*)d_in[14];
    const float* bn1_g = (const float*)d_in[15];
    const float* bn1_b = (const float*)d_in[16];
    const float* bn1_m = (const float*)d_in[17];
    const float* bn1_v = (const float*)d_in[18];
    const float* sh_w  = (const float*)d_in[19];
    const float* sh_b  = (const float*)d_in[20];
    const float* bn2_g = (const float*)d_in[21];
    const float* bn2_b = (const float*)d_in[22];
    const float* bn2_m = (const float*)d_in[23];
    const float* bn2_v = (const float*)d_in[24];
    const float* last_w  = (const float*)d_in[25];
    const float* last_b  = (const float*)d_in[26];
    const float* last2_w = (const float*)d_in[27];
    const float* last2_b = (const float*)d_in[28];
    float* out = (float*)d_out;

    float *p_xres, *p_y, *p_cat;
    cudaGetSymbolAddress((void**)&p_xres, g_xres);
    cudaGetSymbolAddress((void**)&p_y, g_y);
    cudaGetSymbolAddress((void**)&p_cat, g_cat);

    const int DSM16 = 8 * 18 * 34 * 4;   // conv_up (TH=16)
    const int DSM32 = 8 * 34 * 34 * 4;   // conv_sh (TH=32) + conv_last
    cudaFuncSetAttribute(conv3x3_v3_kernel<32, 8, 16>, cudaFuncAttributeMaxDynamicSharedMemorySize, DSM16);
    cudaFuncSetAttribute(conv3x3_v3_kernel<16, 8, 32>, cudaFuncAttributeMaxDynamicSharedMemorySize, DSM32);
    cudaFuncSetAttribute(conv_last_fused_kernel, cudaFuncAttributeMaxDynamicSharedMemorySize, DSM32);

    sigmoid4_kernel<<<(NB * N2 / 4 + 255) / 256, 256>>>(
        (const float4*)logits, (float4*)(out + (size_t)NB * N1), NB * N2 / 4);
    topk_mask_kernel<<<NB, 256>>>(logits);
    zero_gxsq_kernel<<<1, 512>>>();
    // ConvNeXt block
    dwconv_v3_kernel<<<dim3(4, 2, NB * 32), 256>>>(feats4x, dw_w, dw_b);
    lnpw1_kernel<<<(NB * N4) / 256, 256>>>(ln_g, ln_b, pw1_w, pw1_b);
    grn_kernel<<<1, 512>>>();
    block2_kernel<<<(NB * N4) / 256, 256>>>(feats4x, grn_g, grn_b, pw2_w, pw2_b);
    // up branch: conv 32->8 + bn1 @128^2 (32x16 tiles -> 512 blocks)
    conv3x3_v3_kernel<32, 8, 16><<<dim3(4, 8, NB), 256, DSM16>>>(p_xres, 32, up_w, up_b,
        bn1_g, bn1_b, bn1_m, bn1_v, 1, p_y, 8, 0, 128, 128);
    // shortcut branch: conv 16->8 + bn2 + relu @256^2 into cat ch 8..15
    conv3x3_v3_kernel<16, 8, 32><<<dim3(8, 8, NB), 256, DSM32>>>(feats2x, 16, sh_w, sh_b,
        bn2_g, bn2_b, bn2_m, bn2_v, 2, p_cat, 16, 8, 256, 256);
    // last conv 16->4 @256^2 with fused up2x(y) for ch 0..7
    conv_last_fused_kernel<<<dim3(8, 8, NB), 256, DSM32>>>(last_w, last_b);
    // fused upsample + 5x5 + sigmoid -> output part 1
    conv5x5up_sig_kernel<<<dim3(16, 16, NB), 256>>>(last2_w, last2_b, out);
}

// round 6
// speedup vs baseline: 2.0076x; 1.0102x over previous
#include <cuda_runtime.h>
#include <math.h>

#define NB 16
#define N4 (128*128)
#define N2 (256*256)
#define N1 (512*512)
#define KTOP 819

// ---------------- scratch (device globals) ----------------
__device__ float g_mask[NB * N4];
__device__ float g_dwout[NB * 32 * N4];
__device__ float g_xh1[NB * N4 * 32];
__device__ float g_gxsq[NB * 32];
__device__ float g_nx[NB * 32];
__device__ float g_xres[NB * 32 * N4];
__device__ float g_y[NB * 8 * N4];
__device__ float g_z[NB * 4 * N2];

// ---------------- constant weights ----------------
__constant__ float c_dw_w[32 * 49];      // depthwise 7x7
__constant__ float c_up_w[8 * 32 * 9];   // conv_up 32->8
__constant__ float c_sh_w[8 * 16 * 9];   // conv_sh 16->8
__constant__ float c_last_w[4 * 16 * 9]; // conv_last 16->4
__constant__ float c_l2_w[4 * 25];       // conv 5x5 4->1

__device__ __forceinline__ float sigmoidf_(float x) { return 1.0f / (1.0f + expf(-x)); }

// ---------------- sigmoid (output part 2) ----------------
__global__ void sigmoid4_kernel(const float4* __restrict__ in, float4* __restrict__ out, int n4) {
    int i = blockIdx.x * 256 + threadIdx.x;
    if (i < n4) {
        float4 v = in[i];
        out[i] = make_float4(sigmoidf_(v.x), sigmoidf_(v.y), sigmoidf_(v.z), sigmoidf_(v.w));
    }
}

// ---------------- top-k threshold + mask ----------------
__global__ __launch_bounds__(256) void topk_mask_kernel(const float* __restrict__ logits) {
    int b = blockIdx.x;
    int tid = threadIdx.x;
    unsigned key[64];
    const float* lp = logits + (size_t)b * N2;
#pragma unroll
    for (int i = 0; i < 64; i++) {
        int idx = tid + i * 256;
        int r = idx >> 7, c = idx & 127;
        float v = lp[(r * 2) * 256 + c * 2];
        unsigned u = __float_as_uint(v);
        key[i] = (u & 0x80000000u) ? ~u : (u | 0x80000000u);
    }
    __shared__ int red[8];
    unsigned lo = 0u, hi = 0xFFFFFFFFu;
    while (lo < hi) {
        unsigned d = hi - lo;
        unsigned mid = lo + (d >> 1) + (d & 1u);
        int cnt = 0;
#pragma unroll
        for (int i = 0; i < 64; i++) cnt += (key[i] >= mid) ? 1 : 0;
        for (int off = 16; off; off >>= 1) cnt += __shfl_xor_sync(0xffffffffu, cnt, off);
        if ((tid & 31) == 0) red[tid >> 5] = cnt;
        __syncthreads();
        int total = red[0] + red[1] + red[2] + red[3] + red[4] + red[5] + red[6] + red[7];
        if (total >= KTOP) lo = mid; else hi = mid - 1;
        __syncthreads();
    }
#pragma unroll
    for (int i = 0; i < 64; i++)
        g_mask[b * N4 + tid + i * 256] = (key[i] > lo) ? 1.0f : 0.0f;
}

__global__ void zero_gxsq_kernel() {
    if (threadIdx.x < NB * 32) g_gxsq[threadIdx.x] = 0.0f;
}

// ---------------- depthwise 7x7 conv v4: 4x4 px/thread, constant weights ----------------
// tile 64x64; grid (2, 2, NB*32) = 2048 blocks, 256 threads.
__global__ __launch_bounds__(256) void dwconv_v4_kernel(
    const float* __restrict__ feats4x, const float* __restrict__ dw_b) {
    __shared__ float s_t[70 * 70];
    int tid = threadIdx.x;
    int tx = tid & 15, ty = tid >> 4;
    int bc = blockIdx.z;
    int b = bc >> 5, ci = bc & 31;
    int h0 = blockIdx.y * 64, w0 = blockIdx.x * 64;
    const float* ip = feats4x + ((size_t)(b * 32 + ci)) * N4;
    for (int i = tid; i < 70 * 70; i += 256) {
        int r = i / 70, c = i - r * 70;
        int gh = h0 + r - 3, gw = w0 + c - 3;
        s_t[i] = (gh >= 0 && gh < 128 && gw >= 0 && gw < 128) ? ip[gh * 128 + gw] : 0.0f;
    }
    __syncthreads();

    const float* wc = c_dw_w + ci * 49;   // uniform -> LDC/LDCU path
    int bty = 4 * ty, btx = 4 * tx;
    float a[4][4];
#pragma unroll
    for (int r = 0; r < 4; r++)
#pragma unroll
        for (int c = 0; c < 4; c++) a[r][c] = 0.0f;

#pragma unroll
    for (int ir = 0; ir < 10; ir++) {
        float t[10];
        const float* row = s_t + (bty + ir) * 70 + btx;
#pragma unroll
        for (int q = 0; q < 5; q++) {
            float2 p = *reinterpret_cast<const float2*>(row + 2 * q);
            t[2 * q] = p.x; t[2 * q + 1] = p.y;
        }
#pragma unroll
        for (int kh = 0; kh < 7; kh++) {
            int r = ir - kh;
            if (r >= 0 && r < 4) {
#pragma unroll
                for (int kw = 0; kw < 7; kw++) {
                    float w = wc[kh * 7 + kw];
                    a[r][0] = fmaf(t[kw + 0], w, a[r][0]);
                    a[r][1] = fmaf(t[kw + 1], w, a[r][1]);
                    a[r][2] = fmaf(t[kw + 2], w, a[r][2]);
                    a[r][3] = fmaf(t[kw + 3], w, a[r][3]);
                }
            }
        }
    }
    float bias = dw_b[ci];
    float* op = g_dwout + ((size_t)(b * 32 + ci)) * N4 + (h0 + bty) * 128 + w0 + btx;
#pragma unroll
    for (int r = 0; r < 4; r++)
        *reinterpret_cast<float4*>(op + r * 128) =
            make_float4(a[r][0] + bias, a[r][1] + bias, a[r][2] + bias, a[r][3] + bias);
}

// ---------------- mask + LN + pw1 + gelu + sumsq ----------------
__global__ __launch_bounds__(256) void lnpw1_kernel(
    const float* __restrict__ ln_g, const float* __restrict__ ln_b,
    const float* __restrict__ pw1_w, const float* __restrict__ pw1_b) {
    __shared__ float s_pw1[1024];
    __shared__ float s_lng[32], s_lnb[32], s_pb[32];
    __shared__ float s_bsum[32];
    int tid = threadIdx.x;
    for (int i = tid; i < 1024; i += 256) s_pw1[i] = pw1_w[i];
    if (tid < 32) { s_lng[tid] = ln_g[tid]; s_lnb[tid] = ln_b[tid]; s_pb[tid] = pw1_b[tid]; s_bsum[tid] = 0.0f; }
    __syncthreads();

    int p = blockIdx.x * 256 + tid;
    int b = p >> 14, sp = p & 16383;
    float v[32];
#pragma unroll
    for (int c = 0; c < 32; c++) v[c] = g_dwout[((size_t)(b * 32 + c)) * N4 + sp];
    float m = g_mask[p];
    float mu = 0.0f;
#pragma unroll
    for (int c = 0; c < 32; c++) { v[c] *= m; mu += v[c]; }
    mu *= (1.0f / 32.0f);
    float var = 0.0f;
#pragma unroll
    for (int c = 0; c < 32; c++) { float d = v[c] - mu; var = fmaf(d, d, var); }
    var *= (1.0f / 32.0f);
    float rs = rsqrtf(var + 1e-6f);
#pragma unroll
    for (int c = 0; c < 32; c++)
        v[c] = ((v[c] - mu) * rs * s_lng[c] + s_lnb[c]) * m;

    float4* dst = reinterpret_cast<float4*>(g_xh1 + (size_t)p * 32);
    const float4* wf4 = reinterpret_cast<const float4*>(s_pw1);
#pragma unroll
    for (int jq = 0; jq < 8; jq++) {
        float y4[4];
#pragma unroll
        for (int u = 0; u < 4; u++) {
            int j = jq * 4 + u;
            float t = s_pb[j];
#pragma unroll
            for (int cq = 0; cq < 8; cq++) {
                float4 w = wf4[j * 8 + cq];
                t = fmaf(v[4 * cq], w.x, t);
                t = fmaf(v[4 * cq + 1], w.y, t);
                t = fmaf(v[4 * cq + 2], w.z, t);
                t = fmaf(v[4 * cq + 3], w.w, t);
            }
            float g = 0.5f * t * (1.0f + erff(t * 0.70710678118654752f));
            y4[u] = g;
            float sq = g * g;
            for (int off = 16; off; off >>= 1) sq += __shfl_xor_sync(0xffffffffu, sq, off);
            if ((tid & 31) == 0) atomicAdd(&s_bsum[j], sq);
        }
        dst[jq] = make_float4(y4[0], y4[1], y4[2], y4[3]);
    }
    __syncthreads();
    if (tid < 32) atomicAdd(&g_gxsq[b * 32 + tid], s_bsum[tid]);
}

// ---------------- GRN stats ----------------
__global__ void grn_kernel() {
    int b = threadIdx.x >> 5;
    int lane = threadIdx.x & 31;
    if (b < NB) {
        float g = sqrtf(g_gxsq[b * 32 + lane]);
        float s = g;
        for (int off = 16; off; off >>= 1) s += __shfl_xor_sync(0xffffffffu, s, off);
        float mean = s * (1.0f / 32.0f);
        g_nx[b * 32 + lane] = g / (mean + 1e-6f);
    }
}

// ---------------- block2: GRN + pw2 + residual ----------------
__global__ __launch_bounds__(256) void block2_kernel(
    const float* __restrict__ feats4x,
    const float* __restrict__ grn_g, const float* __restrict__ grn_b,
    const float* __restrict__ pw2_w, const float* __restrict__ pw2_b) {
    __shared__ float s_pw2[1024];
    __shared__ float s_gg[32], s_gb[32], s_pb[32];
    int tid = threadIdx.x;
    for (int i = tid; i < 1024; i += 256) s_pw2[i] = pw2_w[i];
    if (tid < 32) { s_gg[tid] = grn_g[tid]; s_gb[tid] = grn_b[tid]; s_pb[tid] = pw2_b[tid]; }
    __syncthreads();
    int p = blockIdx.x * 256 + tid;
    int b = p >> 14, sp = p & 16383;
    float t[32];
    const float4* src = reinterpret_cast<const float4*>(g_xh1 + (size_t)p * 32);
#pragma unroll
    for (int q = 0; q < 8; q++) {
        float4 v = src[q];
        t[4 * q] = v.x; t[4 * q + 1] = v.y; t[4 * q + 2] = v.z; t[4 * q + 3] = v.w;
    }
#pragma unroll
    for (int c = 0; c < 32; c++) {
        float nx = g_nx[b * 32 + c];
        t[c] = fmaf(s_gg[c], t[c] * nx, s_gb[c]) + t[c];
    }
    const float4* wf4 = reinterpret_cast<const float4*>(s_pw2);
#pragma unroll
    for (int j = 0; j < 32; j++) {
        float o = s_pb[j];
#pragma unroll
        for (int cq = 0; cq < 8; cq++) {
            float4 w = wf4[j * 8 + cq];
            o = fmaf(t[4 * cq], w.x, o);
            o = fmaf(t[4 * cq + 1], w.y, o);
            o = fmaf(t[4 * cq + 2], w.z, o);
            o = fmaf(t[4 * cq + 3], w.w, o);
        }
        size_t idx = ((size_t)(b * 32 + j)) * N4 + sp;
        g_xres[idx] = feats4x[idx] + o;
    }
}

// ---------------- conv_up: 32->8 3x3 + bn1 @128^2, constant weights ----------------
// tile 32w x 16h, grid (4,8,NB), 8-channel phases in shared.
__global__ __launch_bounds__(256) void conv_up_kernel(
    const float* __restrict__ up_b,
    const float* __restrict__ bn1_g, const float* __restrict__ bn1_b,
    const float* __restrict__ bn1_m, const float* __restrict__ bn1_v) {
    constexpr int CH = 18 * 34;   // 612
    __shared__ float s_in[8 * CH];
    int tid = threadIdx.x;
    int tx = tid & 15, ty = tid >> 4;
    int b = blockIdx.z;
    int h0 = blockIdx.y * 16, w0 = blockIdx.x * 32;
    float acc[8][2];
#pragma unroll
    for (int o = 0; o < 8; o++) { acc[o][0] = 0.f; acc[o][1] = 0.f; }

    int btx = 2 * tx;
#pragma unroll 1
    for (int phase = 0; phase < 4; phase++) {
        __syncthreads();
        const float* bp = g_xres + ((size_t)(b * 32 + phase * 8)) * N4;
        for (int i = tid; i < 8 * CH; i += 256) {
            int ch = i / CH, j = i - ch * CH;
            int r = j / 34, c = j - r * 34;
            int gh = h0 + r - 1, gw = w0 + c - 1;
            s_in[i] = (gh >= 0 && gh < 128 && gw >= 0 && gw < 128)
                      ? bp[(size_t)ch * N4 + gh * 128 + gw] : 0.0f;
        }
        __syncthreads();
#pragma unroll 1
        for (int ci8 = 0; ci8 < 8; ci8++) {
            int ci = phase * 8 + ci8;
            const float* st = s_in + ci8 * CH;
            float t[12];
#pragma unroll
            for (int r = 0; r < 3; r++) {
                float2 p0 = *reinterpret_cast<const float2*>(st + (ty + r) * 34 + btx);
                float2 p1 = *reinterpret_cast<const float2*>(st + (ty + r) * 34 + btx + 2);
                t[r * 4 + 0] = p0.x; t[r * 4 + 1] = p0.y; t[r * 4 + 2] = p1.x; t[r * 4 + 3] = p1.y;
            }
#pragma unroll
            for (int o = 0; o < 8; o++) {
                const float* w = c_up_w + (o * 32 + ci) * 9;
#pragma unroll
                for (int c = 0; c < 2; c++) {
                    float a = acc[o][c];
                    a = fmaf(t[0 + c + 0], w[0], a);
                    a = fmaf(t[0 + c + 1], w[1], a);
                    a = fmaf(t[0 + c + 2], w[2], a);
                    a = fmaf(t[4 + c + 0], w[3], a);
                    a = fmaf(t[4 + c + 1], w[4], a);
                    a = fmaf(t[4 + c + 2], w[5], a);
                    a = fmaf(t[8 + c + 0], w[6], a);
                    a = fmaf(t[8 + c + 1], w[7], a);
                    a = fmaf(t[8 + c + 2], w[8], a);
                    acc[o][c] = a;
                }
            }
        }
    }
#pragma unroll
    for (int o = 0; o < 8; o++) {
        float sc = bn1_g[o] * rsqrtf(bn1_v[o] + 1e-5f);
        float sh = bn1_b[o] - bn1_m[o] * sc;
        float r0 = fmaf(acc[o][0] + up_b[o], sc, sh);
        float r1 = fmaf(acc[o][1] + up_b[o], sc, sh);
        float* op = g_y + ((size_t)(b * 8 + o)) * N4 + (h0 + ty) * 128 + w0 + btx;
        *reinterpret_cast<float2*>(op) = make_float2(r0, r1);
    }
}

// ---------------- fused: conv_sh(16->8)+bn2+relu, up2x(y), conv_last(16->4) @256^2 ----------------
// grid (8,8,NB), 256 threads, 32x32 output tile.
// dyn smem buf: 16*1296 floats (feats2x 36x36 x16ch), reused as [s 8*1156 | y_up 8*1156].
__global__ __launch_bounds__(256) void conv_shlast_kernel(
    const float* __restrict__ feats2x,
    const float* __restrict__ sh_b,
    const float* __restrict__ bn2_g, const float* __restrict__ bn2_b,
    const float* __restrict__ bn2_m, const float* __restrict__ bn2_v,
    const float* __restrict__ last_b) {
    extern __shared__ float buf[];
    __shared__ float s_y8[8 * 324];
    int tid = threadIdx.x;
    int tx = tid & 15, ty = tid >> 4;
    int b = blockIdx.z;
    int h0 = blockIdx.y * 32, w0 = blockIdx.x * 32;

    // stage y tiles 18x18 (clamped) for up2x
    int ybase = h0 / 2 - 1, xbase = w0 / 2 - 1;
    for (int i = tid; i < 8 * 324; i += 256) {
        int ch = i / 324, j = i - ch * 324;
        int r = j / 18, c = j - r * 18;
        int gy = ybase + r; gy = gy < 0 ? 0 : (gy > 127 ? 127 : gy);
        int gx = xbase + c; gx = gx < 0 ? 0 : (gx > 127 ? 127 : gx);
        s_y8[i] = g_y[((size_t)(b * 8 + ch)) * N4 + gy * 128 + gx];
    }
    // stage feats2x 36x36 x 16ch (zero OOB)
    for (int i = tid; i < 16 * 1296; i += 256) {
        int ch = i / 1296, j = i - ch * 1296;
        int r = j / 36, c = j - r * 36;
        int gh = h0 + r - 2, gw = w0 + c - 2;
        buf[i] = (gh >= 0 && gh < 256 && gw >= 0 && gw < 256)
                 ? feats2x[((size_t)(b * 16 + ch)) * N2 + gh * 256 + gw] : 0.0f;
    }
    __syncthreads();

    // compute s = relu(bn2(conv3x3(feats2x))) on 34x34 tile, in registers
    float sacc[5][8];
#pragma unroll
    for (int it = 0; it < 5; it++) {
        int idx = tid + it * 256;
#pragma unroll
        for (int o = 0; o < 8; o++) sacc[it][o] = 0.0f;
        if (idx < 1156) {
            int r = idx / 34, c = idx - r * 34;
            const float* base = buf + r * 36 + c;
#pragma unroll 1
            for (int ci = 0; ci < 16; ci++) {
                const float* tp = base + ci * 1296;
                float t0 = tp[0],  t1 = tp[1],  t2 = tp[2];
                float t3 = tp[36], t4 = tp[37], t5 = tp[38];
                float t6 = tp[72], t7 = tp[73], t8 = tp[74];
#pragma unroll
                for (int o = 0; o < 8; o++) {
                    const float* w = c_sh_w + (o * 16 + ci) * 9;
                    float a = sacc[it][o];
                    a = fmaf(t0, w[0], a); a = fmaf(t1, w[1], a); a = fmaf(t2, w[2], a);
                    a = fmaf(t3, w[3], a); a = fmaf(t4, w[4], a); a = fmaf(t5, w[5], a);
                    a = fmaf(t6, w[6], a); a = fmaf(t7, w[7], a); a = fmaf(t8, w[8], a);
                    sacc[it][o] = a;
                }
            }
        }
    }
    __syncthreads();   // everyone done reading feats2x; buf reusable

    // write s (zero where tile pos is outside image), layout: buf[o*1156 + idx]
#pragma unroll
    for (int it = 0; it < 5; it++) {
        int idx = tid + it * 256;
        if (idx < 1156) {
            int r = idx / 34, c = idx - r * 34;
            int gy = h0 - 1 + r, gx = w0 - 1 + c;
            bool valid = (gy >= 0 && gy < 256 && gx >= 0 && gx < 256);
#pragma unroll
            for (int o = 0; o < 8; o++) {
                float sc = bn2_g[o] * rsqrtf(bn2_v[o] + 1e-5f);
                float sh = bn2_b[o] - bn2_m[o] * sc;
                float v = fmaf(sacc[it][o] + sh_b[o], sc, sh);
                v = fmaxf(v, 0.0f);
                buf[o * 1156 + idx] = valid ? v : 0.0f;
            }
        }
    }
    // build up2x(y) 34x34 x8ch at buf + 8*1156
    float* yup = buf + 8 * 1156;
    for (int i = tid; i < 8 * 1156; i += 256) {
        int ch = i / 1156, j = i - ch * 1156;
        int r = j / 34, c = j - r * 34;
        int oy = h0 - 1 + r, ox = w0 - 1 + c;
        float v = 0.0f;
        if (oy >= 0 && oy < 256 && ox >= 0 && ox < 256) {
            int my = oy >> 1, mx = ox >> 1;
            int oyo = oy & 1, oxo = ox & 1;
            int gy0 = oyo ? my : my - 1;  int gy1 = oyo ? my + 1 : my;
            float wy1 = oyo ? 0.25f : 0.75f;
            int gx0 = oxo ? mx : mx - 1;  int gx1 = oxo ? mx + 1 : mx;
            float wx1 = oxo ? 0.25f : 0.75f;
            gy0 = gy0 < 0 ? 0 : gy0;  gy1 = gy1 > 127 ? 127 : gy1;
            gx0 = gx0 < 0 ? 0 : gx0;  gx1 = gx1 > 127 ? 127 : gx1;
            int ly0 = gy0 - ybase, ly1 = gy1 - ybase;
            int lx0 = gx0 - xbase, lx1 = gx1 - xbase;
            const float* yp = s_y8 + ch * 324;
            float v00 = yp[ly0 * 18 + lx0], v01 = yp[ly0 * 18 + lx1];
            float v10 = yp[ly1 * 18 + lx0], v11 = yp[ly1 * 18 + lx1];
            v = (1.0f - wy1) * ((1.0f - wx1) * v00 + wx1 * v01)
              + wy1 * ((1.0f - wx1) * v10 + wx1 * v11);
        }
        yup[i] = v;
    }
    __syncthreads();

    // final conv: ch 0..7 = y_up (yup), ch 8..15 = s (buf)
    int bty = 2 * ty, btx = 2 * tx;
    float acc[4][4];
#pragma unroll
    for (int o = 0; o < 4; o++)
#pragma unroll
        for (int u = 0; u < 4; u++) acc[o][u] = 0.0f;

#pragma unroll 1
    for (int phase = 0; phase < 2; phase++) {
        const float* src = (phase == 0) ? yup : buf;
#pragma unroll 1
        for (int ci8 = 0; ci8 < 8; ci8++) {
            int ci = phase * 8 + ci8;
            const float* st = src + ci8 * 1156;
            float t[16];
#pragma unroll
            for (int r = 0; r < 4; r++) {
                float2 p0 = *reinterpret_cast<const float2*>(st + (bty + r) * 34 + btx);
                float2 p1 = *reinterpret_cast<const float2*>(st + (bty + r) * 34 + btx + 2);
                t[r * 4 + 0] = p0.x; t[r * 4 + 1] = p0.y; t[r * 4 + 2] = p1.x; t[r * 4 + 3] = p1.y;
            }
            int wci = (phase == 0) ? ci : ci;   // cat order matches weight ci
#pragma unroll
            for (int o = 0; o < 4; o++) {
                const float* w = c_last_w + (o * 16 + wci) * 9;
#pragma unroll
                for (int r = 0; r < 2; r++)
#pragma unroll
                    for (int c = 0; c < 2; c++) {
                        float a = acc[o][r * 2 + c];
                        a = fmaf(t[(r + 0) * 4 + c + 0], w[0], a);
                        a = fmaf(t[(r + 0) * 4 + c + 1], w[1], a);
                        a = fmaf(t[(r + 0) * 4 + c + 2], w[2], a);
                        a = fmaf(t[(r + 1) * 4 + c + 0], w[3], a);
                        a = fmaf(t[(r + 1) * 4 + c + 1], w[4], a);
                        a = fmaf(t[(r + 1) * 4 + c + 2], w[5], a);
                        a = fmaf(t[(r + 2) * 4 + c + 0], w[6], a);
                        a = fmaf(t[(r + 2) * 4 + c + 1], w[7], a);
                        a = fmaf(t[(r + 2) * 4 + c + 2], w[8], a);
                        acc[o][r * 2 + c] = a;
                    }
            }
        }
    }
#pragma unroll
    for (int o = 0; o < 4; o++) {
        float bs = last_b[o];
        float* op = g_z + ((size_t)(b * 4 + o)) * N2 + (h0 + bty) * 256 + w0 + btx;
#pragma unroll
        for (int r = 0; r < 2; r++)
            *reinterpret_cast<float2*>(op + r * 256) =
                make_float2(acc[o][r * 2 + 0] + bs, acc[o][r * 2 + 1] + bs);
    }
}

// ---------------- fused up2x(z) -> conv5x5 -> sigmoid ----------------
__global__ __launch_bounds__(256) void conv5x5up_sig_kernel(
    const float* __restrict__ bias, float* __restrict__ out) {
    __shared__ float s_uz[36 * 36];
    int tid = threadIdx.x;
    int tx = tid & 15, ty = tid >> 4;
    int b = blockIdx.z, h0 = blockIdx.y * 32, w0 = blockIdx.x * 32;
    float acc[4] = {0.f, 0.f, 0.f, 0.f};
    int bty = 2 * ty, btx = 2 * tx;
    for (int ch = 0; ch < 4; ch++) {
        __syncthreads();
        const float* zp = g_z + ((size_t)(b * 4 + ch)) * N2;
        for (int i = tid; i < 36 * 36; i += 256) {
            int r = i / 36, c = i - r * 36;
            int oy = h0 - 2 + r, ox = w0 - 2 + c;
            float v = 0.0f;
            if (oy >= 0 && oy < 512 && ox >= 0 && ox < 512) {
                float fy = oy * 0.5f - 0.25f, fx = ox * 0.5f - 0.25f;
                int y0 = (int)floorf(fy), x0 = (int)floorf(fx);
                float wy = fy - (float)y0, wx = fx - (float)x0;
                int y0c = y0 < 0 ? 0 : y0;
                int y1c = (y0 + 1) > 255 ? 255 : (y0 + 1);
                int x0c = x0 < 0 ? 0 : x0;
                int x1c = (x0 + 1) > 255 ? 255 : (x0 + 1);
                float v00 = zp[y0c * 256 + x0c], v01 = zp[y0c * 256 + x1c];
                float v10 = zp[y1c * 256 + x0c], v11 = zp[y1c * 256 + x1c];
                v = (1.0f - wy) * ((1.0f - wx) * v00 + wx * v01)
                  + wy * ((1.0f - wx) * v10 + wx * v11);
            }
            s_uz[i] = v;
        }
        __syncthreads();
        float t[36];
#pragma unroll
        for (int r = 0; r < 6; r++)
#pragma unroll
            for (int c = 0; c < 6; c++)
                t[r * 6 + c] = s_uz[(bty + r) * 36 + btx + c];
        const float* w = c_l2_w + ch * 25;
#pragma unroll
        for (int r = 0; r < 2; r++)
#pragma unroll
            for (int c = 0; c < 2; c++) {
                float a = acc[r * 2 + c];
#pragma unroll
                for (int kh = 0; kh < 5; kh++)
#pragma unroll
                    for (int kw = 0; kw < 5; kw++)
                        a = fmaf(t[(r + kh) * 6 + c + kw], w[kh * 5 + kw], a);
                acc[r * 2 + c] = a;
            }
    }
    float bs = bias[0];
    float* op = out + (size_t)b * N1 + (h0 + bty) * 512 + w0 + btx;
#pragma unroll
    for (int r = 0; r < 2; r++) {
        float r0 = sigmoidf_(acc[r * 2 + 0] + bs);
        float r1 = sigmoidf_(acc[r * 2 + 1] + bs);
        *reinterpret_cast<float2*>(op + r * 512) = make_float2(r0, r1);
    }
}

// ---------------- launcher ----------------
extern "C" void kernel_launch(void* const* d_in, const int* in_sizes, int n_in,
                              void* d_out, int out_size) {
    const float* feats4x = (const float*)d_in[0];
    const float* feats2x = (const float*)d_in[1];
    const float* logits  = (const float*)d_in[2];
    const float* dw_w  = (const float*)d_in[3];
    const float* dw_b  = (const float*)d_in[4];
    const float* ln_g  = (const float*)d_in[5];
    const float* ln_b  = (const float*)d_in[6];
    const float* pw1_w = (const float*)d_in[7];
    const float* pw1_b = (const float*)d_in[8];
    const float* grn_g = (const float*)d_in[9];
    const float* grn_b = (const float*)d_in[10];
    const float* pw2_w = (const float*)d_in[11];
    const float* pw2_b = (const float*)d_in[12];
    const float* up_w  = (const float*)d_in[13];
    const float* up_b  = (const float*)d_in[14];
    const float* bn1_g = (const float*)d_in[15];
    const float* bn1_b = (const float*)d_in[16];
    const float* bn1_m = (const float*)d_in[17];
    const float* bn1_v = (const float*)d_in[18];
    const float* sh_w  = (const float*)d_in[19];
    const float* sh_b  = (const float*)d_in[20];
    const float* bn2_g = (const float*)d_in[21];
    const float* bn2_b = (const float*)d_in[22];
    const float* bn2_m = (const float*)d_in[23];
    const float* bn2_v = (const float*)d_in[24];
    const float* last_w  = (const float*)d_in[25];
    const float* last_b  = (const float*)d_in[26];
    const float* last2_w = (const float*)d_in[27];
    const float* last2_b = (const float*)d_in[28];
    float* out = (float*)d_out;

    // weights -> constant (device-to-device async copies; graph-capturable)
    cudaMemcpyToSymbolAsync(c_dw_w,   dw_w,   32 * 49 * 4,     0, cudaMemcpyDeviceToDevice, 0);
    cudaMemcpyToSymbolAsync(c_up_w,   up_w,   8 * 32 * 9 * 4,  0, cudaMemcpyDeviceToDevice, 0);
    cudaMemcpyToSymbolAsync(c_sh_w,   sh_w,   8 * 16 * 9 * 4,  0, cudaMemcpyDeviceToDevice, 0);
    cudaMemcpyToSymbolAsync(c_last_w, last_w, 4 * 16 * 9 * 4,  0, cudaMemcpyDeviceToDevice, 0);
    cudaMemcpyToSymbolAsync(c_l2_w,   last2_w, 4 * 25 * 4,     0, cudaMemcpyDeviceToDevice, 0);

    const int DSM_SHLAST = 16 * 1296 * 4;   // 82944 B
    cudaFuncSetAttribute(conv_shlast_kernel, cudaFuncAttributeMaxDynamicSharedMemorySize, DSM_SHLAST);

    sigmoid4_kernel<<<(NB * N2 / 4 + 255) / 256, 256>>>(
        (const float4*)logits, (float4*)(out + (size_t)NB * N1), NB * N2 / 4);
    topk_mask_kernel<<<NB, 256>>>(logits);
    zero_gxsq_kernel<<<1, 512>>>();
    // ConvNeXt block
    dwconv_v4_kernel<<<dim3(2, 2, NB * 32), 256>>>(feats4x, dw_b);
    lnpw1_kernel<<<(NB * N4) / 256, 256>>>(ln_g, ln_b, pw1_w, pw1_b);
    grn_kernel<<<1, 512>>>();
    block2_kernel<<<(NB * N4) / 256, 256>>>(feats4x, grn_g, grn_b, pw2_w, pw2_b);
    // up branch
    conv_up_kernel<<<dim3(4, 8, NB), 256>>>(up_b, bn1_g, bn1_b, bn1_m, bn1_v);
    // fused shortcut conv + y-upsample + last conv
    conv_shlast_kernel<<<dim3(8, 8, NB), 256, DSM_SHLAST>>>(
        feats2x, sh_b, bn2_g, bn2_b, bn2_m, bn2_v, last_b);
    // fused z-upsample + 5x5 + sigmoid
    conv5x5up_sig_kernel<<<dim3(16, 16, NB), 256>>>(last2_b, out);
}